// round 1
// baseline (speedup 1.0000x reference)
#include <cuda_runtime.h>
#include <math.h>

// ---------------- problem constants ----------------
#define BB 4
#define TT_SEQ 4096
#define DD 1024
#define NTOK (BB*TT_SEQ)          // 16384
#define NBLK 16
#define BIP 192                   // w_post block input width
#define RANKR 64
#define NMEM 128
#define LC 128                    // scan chunk length
#define NC (TT_SEQ/LC)            // 32 chunks
#define EPSV 1.1920929e-07f
#define TTOK 64                   // token tile for GEMMs
#define SP 68                     // padded smem row stride (floats), 16B-aligned rows

// ---------------- scratch (device globals; no allocation) ----------------
__device__ float g_e    [NTOK*DD];
__device__ float g_drive[NTOK*DD];
__device__ float g_hd   [NTOK*DD];
__device__ float g_h    [NTOK*DD];
__device__ float g_hn   [NTOK*DD];
__device__ float g_r    [NTOK*DD];
__device__ float g_t    [NTOK*RANKR];
__device__ float g_csum [BB*NC*DD];
__device__ float g_carry[BB*NC*DD];

__device__ __forceinline__ float siluf(float x) {
    return x / (1.0f + __expf(-x));
}

// ---------------- shared helpers ----------------
// Load a 64x64 fp32 tile (rows of length rowstride at `base`) TRANSPOSED into
// smem s[col][row] with row stride SP. 256 threads.
__device__ __forceinline__ void load_tile_T(float* s, const float* __restrict__ base,
                                            size_t rowstride, int tid) {
#pragma unroll
    for (int it = 0; it < 4; ++it) {
        int idx4 = tid + it * 256;
        int i  = idx4 >> 4;            // row (token / output-row)
        int j0 = (idx4 & 15) << 2;     // col (k)
        float4 v = *reinterpret_cast<const float4*>(base + (size_t)i * rowstride + j0);
        s[(j0 + 0) * SP + i] = v.x;
        s[(j0 + 1) * SP + i] = v.y;
        s[(j0 + 2) * SP + i] = v.z;
        s[(j0 + 3) * SP + i] = v.w;
    }
}

__device__ __forceinline__ void mma44(float acc[4][4], float4 a, float4 b) {
    float av[4] = {a.x, a.y, a.z, a.w};
    float bv[4] = {b.x, b.y, b.z, b.w};
#pragma unroll
    for (int i = 0; i < 4; i++)
#pragma unroll
        for (int j = 0; j < 4; j++)
            acc[i][j] = fmaf(av[i], bv[j], acc[i][j]);
}

// acc += A(64tok x 64k) * B(64k x 64out); as = A^T tile, bs = B^T tile (both [k][.])
__device__ __forceinline__ void gemm_tile(float acc[4][4], const float* as,
                                          const float* bs, int ty, int tx) {
#pragma unroll
    for (int k = 0; k < 64; k++) {
        float4 a = *reinterpret_cast<const float4*>(&as[k * SP + ty * 4]);
        float4 b = *reinterpret_cast<const float4*>(&bs[k * SP + tx * 4]);
        mma44(acc, a, b);
    }
}

__device__ __forceinline__ float decay_of(const float* lA, const float* ldt, int d) {
    float z = __expf(lA[d]) * __expf(ldt[d]);
    float a = __expf(-z);
    return fmaxf(a, 1e-6f);   // matches jnp.log(jnp.maximum(a,1e-6)) clamp
}

// ---------------- RMS norm: one CTA (256 thr) per token row of 1024 ----------------
__global__ void k_rmsnorm(const float* __restrict__ x, float* __restrict__ o) {
    int tok = blockIdx.x;
    const float4* xr = reinterpret_cast<const float4*>(x + (size_t)tok * DD);
    float4 v = xr[threadIdx.x];
    float ss = v.x * v.x + v.y * v.y + v.z * v.z + v.w * v.w;
    __shared__ float sred[8];
#pragma unroll
    for (int off = 16; off > 0; off >>= 1) ss += __shfl_xor_sync(0xffffffffu, ss, off);
    int wid = threadIdx.x >> 5, lid = threadIdx.x & 31;
    if (lid == 0) sred[wid] = ss;
    __syncthreads();
    if (wid == 0) {
        float s2 = (lid < 8) ? sred[lid] : 0.0f;
#pragma unroll
        for (int off = 4; off > 0; off >>= 1) s2 += __shfl_xor_sync(0xffffffffu, s2, off);
        if (lid == 0) sred[0] = s2;
    }
    __syncthreads();
    float r = rsqrtf(sred[0] * (1.0f / DD) + EPSV);
    float4 ov = make_float4(v.x * r, v.y * r, v.z * r, v.w * r);
    reinterpret_cast<float4*>(o + (size_t)tok * DD)[threadIdx.x] = ov;
}

// ---------------- G1: drive = silu(bd(e,Wseq)); hd = gain * silu(bd(e,Wdep)) ----------------
__global__ void k_g1(const float* __restrict__ wseq, const float* __restrict__ wdep,
                     const float* __restrict__ lAd, const float* __restrict__ ldtd,
                     const int* __restrict__ kptr) {
    __shared__ float es[64 * SP];
    __shared__ float ws[64 * SP];
    int blk = blockIdx.y;
    int tok0 = blockIdx.x * TTOK;
    int tid = threadIdx.x;
    int ty = tid >> 4, tx = tid & 15;

    load_tile_T(es, g_e + (size_t)tok0 * DD + blk * 64, DD, tid);
    load_tile_T(ws, wseq + (size_t)blk * 64 * 64, 64, tid);
    __syncthreads();

    float as_[4][4] = {}, ad_[4][4] = {};
    gemm_tile(as_, es, ws, ty, tx);
    __syncthreads();
    load_tile_T(ws, wdep + (size_t)blk * 64 * 64, 64, tid);
    __syncthreads();
    gemm_tile(ad_, es, ws, ty, tx);

    float Kf = (float)(*kptr);
#pragma unroll
    for (int jj = 0; jj < 4; jj++) {
        int o = tx * 4 + jj;
        int gch = blk * 64 + o;
        float g;
        if (gch < NMEM) {
            g = Kf;
        } else {
            float z  = __expf(lAd[gch - NMEM]) * __expf(ldtd[gch - NMEM]);
            float a1 = __expf(-z);
            float om = 1.0f - a1;
            if (fabsf(om) < 1e-6f) g = Kf;
            else g = (1.0f - __expf(Kf * __logf(a1))) / fmaxf(om, 1e-8f);
        }
#pragma unroll
        for (int ii = 0; ii < 4; ii++) {
            int tok = tok0 + ty * 4 + ii;
            size_t oidx = (size_t)tok * DD + gch;
            g_drive[oidx] = siluf(as_[ii][jj]);
            g_hd[oidx]    = g * siluf(ad_[ii][jj]);
        }
    }
}

// ---------------- S1: per-chunk local scans + chunk sums ----------------
__global__ void k_s1(const float* __restrict__ lAs, const float* __restrict__ ldts) {
    int c = blockIdx.x;     // chunk
    int b = blockIdx.y;     // batch
    int tid = threadIdx.x;
    float a[4], y[4];
#pragma unroll
    for (int q = 0; q < 4; q++) {
        int d = tid + q * 256;
        a[q] = decay_of(lAs, ldts, d);
        y[q] = 0.0f;
    }
    size_t base = ((size_t)(b * TT_SEQ + c * LC)) * DD;
    for (int s = 0; s < LC; s++) {
        size_t row = base + (size_t)s * DD;
#pragma unroll
        for (int q = 0; q < 4; q++) {
            int d = tid + q * 256;
            y[q] = fmaf(a[q], y[q], g_drive[row + d]);
            g_h[row + d] = y[q];
        }
    }
#pragma unroll
    for (int q = 0; q < 4; q++) {
        int d = tid + q * 256;
        g_csum[((size_t)(b * NC + c)) * DD + d] = y[q];
    }
}

// ---------------- S1b: cross-chunk carry scan (tiny) ----------------
__global__ void k_s1b(const float* __restrict__ lAs, const float* __restrict__ ldts) {
    int gt = blockIdx.x * blockDim.x + threadIdx.x;   // 0..B*D-1
    int b = gt / DD, d = gt % DD;
    float a = decay_of(lAs, ldts, d);
    float aL = __expf(128.0f * __logf(a));
    float carry = 0.0f;
    for (int c = 0; c < NC; c++) {
        size_t idx = ((size_t)(b * NC + c)) * DD + d;
        g_carry[idx] = carry;
        carry = g_csum[idx] + carry * aL;
    }
}

// ---------------- S2: fixup h = local + carry*a^(s+1) + h_depth ----------------
__global__ void k_s2(const float* __restrict__ lAs, const float* __restrict__ ldts) {
    int c = blockIdx.x;
    int b = blockIdx.y;
    int tid = threadIdx.x;
    float a[4], pw[4];
#pragma unroll
    for (int q = 0; q < 4; q++) {
        int d = tid + q * 256;
        a[q] = decay_of(lAs, ldts, d);
        pw[q] = g_carry[((size_t)(b * NC + c)) * DD + d] * a[q];
    }
    size_t base = ((size_t)(b * TT_SEQ + c * LC)) * DD;
    for (int s = 0; s < LC; s++) {
        size_t row = base + (size_t)s * DD;
#pragma unroll
        for (int q = 0; q < 4; q++) {
            int d = tid + q * 256;
            g_h[row + d] = g_h[row + d] + pw[q] + g_hd[row + d];
            pw[q] *= a[q];
        }
    }
}

// ---------------- G2: r = silu(bd(concat[hn,e,shifted_e], w_post)) ----------------
__global__ void k_g2(const float* __restrict__ wpost) {
    __shared__ float is_[64 * SP];
    __shared__ float ws[64 * SP];
    int blk = blockIdx.y;
    int tok0 = blockIdx.x * TTOK;
    int tid = threadIdx.x;
    int ty = tid >> 4, tx = tid & 15;
    float acc[4][4] = {};

    for (int kt = 0; kt < 3; ++kt) {
        // gather input tile from the concat vector, transposed
#pragma unroll
        for (int it = 0; it < 4; ++it) {
            int idx4 = tid + it * 256;
            int i  = idx4 >> 4;
            int j0 = (idx4 & 15) << 2;
            int gcat = blk * BIP + kt * 64 + j0;
            int tok = tok0 + i;
            float4 v;
            if (gcat < 1024) {
                v = *reinterpret_cast<const float4*>(&g_hn[(size_t)tok * DD + gcat]);
            } else if (gcat < 2048) {
                v = *reinterpret_cast<const float4*>(&g_e[(size_t)tok * DD + (gcat - 1024)]);
            } else {
                if ((tok & (TT_SEQ - 1)) == 0) v = make_float4(0.f, 0.f, 0.f, 0.f);
                else v = *reinterpret_cast<const float4*>(&g_e[(size_t)(tok - 1) * DD + (gcat - 2048)]);
            }
            is_[(j0 + 0) * SP + i] = v.x;
            is_[(j0 + 1) * SP + i] = v.y;
            is_[(j0 + 2) * SP + i] = v.z;
            is_[(j0 + 3) * SP + i] = v.w;
        }
        // weight tile: wpost[blk][o][kt*64 + k]
#pragma unroll
        for (int it = 0; it < 4; ++it) {
            int idx4 = tid + it * 256;
            int o  = idx4 >> 4;
            int k0 = (idx4 & 15) << 2;
            float4 v = *reinterpret_cast<const float4*>(
                &wpost[((size_t)blk * 64 + o) * BIP + kt * 64 + k0]);
            ws[(k0 + 0) * SP + o] = v.x;
            ws[(k0 + 1) * SP + o] = v.y;
            ws[(k0 + 2) * SP + o] = v.z;
            ws[(k0 + 3) * SP + o] = v.w;
        }
        __syncthreads();
        gemm_tile(acc, is_, ws, ty, tx);
        __syncthreads();
    }

#pragma unroll
    for (int jj = 0; jj < 4; jj++) {
        int o = tx * 4 + jj;
#pragma unroll
        for (int ii = 0; ii < 4; ii++) {
            int tok = tok0 + ty * 4 + ii;
            g_r[(size_t)tok * DD + blk * 64 + o] = siluf(acc[ii][jj]);
        }
    }
}

// ---------------- G3: t = r @ lr_B^T  (K=1024, out=64) ----------------
__global__ void k_g3(const float* __restrict__ lrB) {
    __shared__ float rs[64 * SP];
    __shared__ float bs[64 * SP];
    int tok0 = blockIdx.x * TTOK;
    int tid = threadIdx.x;
    int ty = tid >> 4, tx = tid & 15;
    float acc[4][4] = {};

    for (int kt = 0; kt < 16; ++kt) {
        load_tile_T(rs, g_r + (size_t)tok0 * DD + kt * 64, DD, tid);
        load_tile_T(bs, lrB + kt * 64, DD, tid);   // lrB[rk][k], rowstride 1024
        __syncthreads();
        gemm_tile(acc, rs, bs, ty, tx);
        __syncthreads();
    }
#pragma unroll
    for (int jj = 0; jj < 4; jj++) {
        int rk = tx * 4 + jj;
#pragma unroll
        for (int ii = 0; ii < 4; ii++) {
            int tok = tok0 + ty * 4 + ii;
            g_t[(size_t)tok * RANKR + rk] = acc[ii][jj];
        }
    }
}

// ---------------- G4: out = x + bd(r, w_local) + t @ lr_A^T ----------------
__global__ void k_g4(const float* __restrict__ x, const float* __restrict__ wloc,
                     const float* __restrict__ lrA, float* __restrict__ out) {
    __shared__ float s0[64 * SP];
    __shared__ float s1[64 * SP];
    int blk = blockIdx.y;
    int tok0 = blockIdx.x * TTOK;
    int tid = threadIdx.x;
    int ty = tid >> 4, tx = tid & 15;
    float acc[4][4] = {};

    // phase 1: block-diagonal local projection
    load_tile_T(s0, g_r + (size_t)tok0 * DD + blk * 64, DD, tid);
    load_tile_T(s1, wloc + (size_t)blk * 64 * 64, 64, tid);
    __syncthreads();
    gemm_tile(acc, s0, s1, ty, tx);
    __syncthreads();

    // phase 2: low-rank up-projection (t[tok][rk] * lrA[blk*64+o][rk])
    load_tile_T(s0, g_t + (size_t)tok0 * RANKR, RANKR, tid);
    load_tile_T(s1, lrA + (size_t)blk * 64 * 64, 64, tid);
    __syncthreads();
    gemm_tile(acc, s0, s1, ty, tx);

#pragma unroll
    for (int jj = 0; jj < 4; jj++) {
        int o = tx * 4 + jj;
#pragma unroll
        for (int ii = 0; ii < 4; ii++) {
            int tok = tok0 + ty * 4 + ii;
            size_t idx = (size_t)tok * DD + blk * 64 + o;
            out[idx] = x[idx] + acc[ii][jj];
        }
    }
}

// ---------------- launch ----------------
extern "C" void kernel_launch(void* const* d_in, const int* in_sizes, int n_in,
                              void* d_out, int out_size) {
    const float* x    = (const float*)d_in[0];
    const int*   actk = (const int*)  d_in[1];
    const float* wseq = (const float*)d_in[2];
    const float* wdep = (const float*)d_in[3];
    const float* wpost= (const float*)d_in[4];
    const float* wloc = (const float*)d_in[5];
    const float* lrA  = (const float*)d_in[6];
    const float* lrB  = (const float*)d_in[7];
    const float* lAs  = (const float*)d_in[8];
    const float* ldts = (const float*)d_in[9];
    const float* lAd  = (const float*)d_in[10];
    const float* ldtd = (const float*)d_in[11];
    float* out = (float*)d_out;

    float* e_ptr; cudaGetSymbolAddress((void**)&e_ptr, g_e);
    float* h_ptr; cudaGetSymbolAddress((void**)&h_ptr, g_h);
    float* hn_ptr; cudaGetSymbolAddress((void**)&hn_ptr, g_hn);

    dim3 gGemm(NTOK / TTOK, NBLK);   // (256, 16)
    dim3 gScan(NC, BB);              // (32, 4)

    k_rmsnorm<<<NTOK, 256>>>(x, e_ptr);
    k_g1<<<gGemm, 256>>>(wseq, wdep, lAd, ldtd, actk);
    k_s1<<<gScan, 256>>>(lAs, ldts);
    k_s1b<<<(BB * DD) / 256, 256>>>(lAs, ldts);
    k_s2<<<gScan, 256>>>(lAs, ldts);
    k_rmsnorm<<<NTOK, 256>>>(h_ptr, hn_ptr);
    k_g2<<<gGemm, 256>>>(wpost);
    k_g3<<<NTOK / TTOK, 256>>>(lrB);
    k_g4<<<gGemm, 256>>>(x, wloc, lrA, out);
}

// round 2
// speedup vs baseline: 2.2012x; 2.2012x over previous
#include <cuda_runtime.h>
#include <math.h>

// ---------------- problem constants ----------------
#define BB 4
#define TT_SEQ 4096
#define DD 1024
#define NTOK (BB*TT_SEQ)          // 16384
#define NBLK 16
#define BIP 192                   // w_post block input width
#define RANKR 64
#define NMEM 128
#define LC 64                     // scan chunk length
#define NC (TT_SEQ/LC)            // 64 chunks
#define EPSV 1.1920929e-07f

// ---------------- scratch (device globals; no allocation) ----------------
__device__ float g_e    [NTOK*DD];
__device__ float g_drive[NTOK*DD];
__device__ float g_hd   [NTOK*DD];
__device__ float g_hn   [NTOK*DD];
__device__ float g_r    [NTOK*DD];
__device__ float g_t    [NTOK*RANKR];
__device__ float g_csum [BB*NC*DD];
__device__ float g_carry[BB*NC*DD];

__device__ __forceinline__ float siluf(float x) {
    return x / (1.0f + __expf(-x));
}

__device__ __forceinline__ unsigned f2tf(float f) {
    unsigned u;
    asm("cvt.rna.tf32.f32 %0, %1;" : "=r"(u) : "f"(f));
    return u;
}

__device__ __forceinline__ float4 decay4(const float* __restrict__ lA,
                                         const float* __restrict__ ldt, int d0) {
    float4 r;
    r.x = fmaxf(__expf(-__expf(lA[d0+0]) * __expf(ldt[d0+0])), 1e-6f);
    r.y = fmaxf(__expf(-__expf(lA[d0+1]) * __expf(ldt[d0+1])), 1e-6f);
    r.z = fmaxf(__expf(-__expf(lA[d0+2]) * __expf(ldt[d0+2])), 1e-6f);
    r.w = fmaxf(__expf(-__expf(lA[d0+3]) * __expf(ldt[d0+3])), 1e-6f);
    return r;
}

// ---------------- tf32 MMA machinery ----------------
// CTA = 256 threads = 8 warps. Tile: M=64 tokens x N=64 outputs, K staged in
// 64-chunks. Warp w: wm = w&3 (m16 tile), wn = w>>2 (n32 half), 4 n8 subtiles.
// smem is fragment-major: per-lane A frag contiguous (LDS.128), B frag (LDS.64).

__device__ __forceinline__ void mma_tf32(float c[4], const unsigned a[4], const unsigned b[2]) {
    asm volatile("mma.sync.aligned.m16n8k8.row.col.f32.tf32.tf32.f32 "
        "{%0,%1,%2,%3}, {%4,%5,%6,%7}, {%8,%9}, {%0,%1,%2,%3};"
        : "+f"(c[0]), "+f"(c[1]), "+f"(c[2]), "+f"(c[3])
        : "r"(a[0]), "r"(a[1]), "r"(a[2]), "r"(a[3]), "r"(b[0]), "r"(b[1]));
}

// stage 64x64 A tile (rows = tokens, cols = k) from row-major source
__device__ __forceinline__ void stage_A(unsigned* sA, const float* __restrict__ base,
                                        int rs, int tid) {
#pragma unroll
    for (int it = 0; it < 4; ++it) {
        int idx4 = tid + it * 256;
        int i  = idx4 >> 4;
        int j0 = (idx4 & 15) << 2;
        float4 v = *reinterpret_cast<const float4*>(base + (size_t)i * rs + j0);
        int mt = i >> 4, rr = i & 15, half = rr >> 3, g = rr & 7;
        int ks = j0 >> 3, hi = (j0 >> 2) & 1;
        unsigned* p = &sA[(((mt * 8 + ks) * 32) + g * 4) * 4 + (half + 2 * hi)];
        p[0]  = f2tf(v.x);
        p[4]  = f2tf(v.y);
        p[8]  = f2tf(v.z);
        p[12] = f2tf(v.w);
    }
}

// stage 64x64 B tile: source rows are outputs n (length-64 k contiguous), stride rs
__device__ __forceinline__ void stage_B(unsigned* sB, const float* __restrict__ base,
                                        int rs, int tid) {
#pragma unroll
    for (int it = 0; it < 4; ++it) {
        int idx4 = tid + it * 256;
        int n  = idx4 >> 4;
        int k0 = (idx4 & 15) << 2;
        float4 v = *reinterpret_cast<const float4*>(base + (size_t)n * rs + k0);
        int nt = n >> 3, g = n & 7;
        int ks = k0 >> 3, hi = (k0 >> 2) & 1;
        unsigned* p = &sB[(((nt * 8 + ks) * 32) + g * 4) * 2 + hi];
        p[0] = f2tf(v.x);
        p[2] = f2tf(v.y);
        p[4] = f2tf(v.z);
        p[6] = f2tf(v.w);
    }
}

__device__ __forceinline__ void mma_chunk(float acc[4][4], const unsigned* sA,
                                          const unsigned* sB, int wm, int wn, int lane) {
#pragma unroll
    for (int ks = 0; ks < 8; ks++) {
        unsigned a[4];
        *reinterpret_cast<uint4*>(a) =
            *reinterpret_cast<const uint4*>(&sA[((wm * 8 + ks) * 32 + lane) * 4]);
#pragma unroll
        for (int nt = 0; nt < 4; nt++) {
            unsigned b[2];
            *reinterpret_cast<uint2*>(b) =
                *reinterpret_cast<const uint2*>(&sB[(((wn * 4 + nt) * 8 + ks) * 32 + lane) * 2]);
            mma_tf32(acc[nt], a, b);
        }
    }
}

// ---------------- RMS norm: x -> e ----------------
__global__ void __launch_bounds__(256) k_rmsnorm(const float* __restrict__ x, float* __restrict__ o) {
    int tok = blockIdx.x;
    const float4* xr = reinterpret_cast<const float4*>(x + (size_t)tok * DD);
    float4 v = xr[threadIdx.x];
    float ss = v.x * v.x + v.y * v.y + v.z * v.z + v.w * v.w;
    __shared__ float sred[8];
#pragma unroll
    for (int off = 16; off > 0; off >>= 1) ss += __shfl_xor_sync(0xffffffffu, ss, off);
    int wid = threadIdx.x >> 5, lid = threadIdx.x & 31;
    if (lid == 0) sred[wid] = ss;
    __syncthreads();
    float tot = sred[0] + sred[1] + sred[2] + sred[3] + sred[4] + sred[5] + sred[6] + sred[7];
    float r = rsqrtf(tot * (1.0f / DD) + EPSV);
    float4 ov = make_float4(v.x * r, v.y * r, v.z * r, v.w * r);
    reinterpret_cast<float4*>(o + (size_t)tok * DD)[threadIdx.x] = ov;
}

// ---------------- gain helper ----------------
__device__ __forceinline__ float gain_of(int gch, float Kf, const float* __restrict__ lAd,
                                         const float* __restrict__ ldtd) {
    if (gch < NMEM) return Kf;
    float a1 = __expf(-__expf(lAd[gch - NMEM]) * __expf(ldtd[gch - NMEM]));
    float om = 1.0f - a1;
    if (fabsf(om) < 1e-6f) return Kf;
    return (1.0f - __expf(Kf * __logf(a1))) / fmaxf(om, 1e-8f);
}

// ---------------- G1: drive = silu(bd(e,Wseq)); hd = gain*silu(bd(e,Wdep)) ----------------
__global__ void __launch_bounds__(256) k_g1(const float* __restrict__ wseq,
                                            const float* __restrict__ wdep,
                                            const float* __restrict__ lAd,
                                            const float* __restrict__ ldtd,
                                            const int* __restrict__ kptr) {
    __shared__ unsigned sA[4096];
    __shared__ unsigned sB1[4096];
    __shared__ unsigned sB2[4096];
    int blk = blockIdx.y;
    int tok0 = blockIdx.x * 64;
    int tid = threadIdx.x, lane = tid & 31, w = tid >> 5, wm = w & 3, wn = w >> 2;

    stage_A(sA, g_e + (size_t)tok0 * DD + blk * 64, DD, tid);
    stage_B(sB1, wseq + (size_t)blk * 4096, 64, tid);
    stage_B(sB2, wdep + (size_t)blk * 4096, 64, tid);
    __syncthreads();

    float as_[4][4] = {}, ad_[4][4] = {};
#pragma unroll
    for (int ks = 0; ks < 8; ks++) {
        unsigned a[4];
        *reinterpret_cast<uint4*>(a) =
            *reinterpret_cast<const uint4*>(&sA[((wm * 8 + ks) * 32 + lane) * 4]);
#pragma unroll
        for (int nt = 0; nt < 4; nt++) {
            unsigned b[2];
            int off = (((wn * 4 + nt) * 8 + ks) * 32 + lane) * 2;
            *reinterpret_cast<uint2*>(b) = *reinterpret_cast<const uint2*>(&sB1[off]);
            mma_tf32(as_[nt], a, b);
            *reinterpret_cast<uint2*>(b) = *reinterpret_cast<const uint2*>(&sB2[off]);
            mma_tf32(ad_[nt], a, b);
        }
    }

    float Kf = (float)(*kptr);
    int g = lane >> 2, t = lane & 3;
    int r0 = tok0 + wm * 16 + g;
#pragma unroll
    for (int nt = 0; nt < 4; nt++) {
        int gch = blk * 64 + (wn * 4 + nt) * 8 + t * 2;
        float gn0 = gain_of(gch, Kf, lAd, ldtd);
        float gn1 = gain_of(gch + 1, Kf, lAd, ldtd);
        float2 dv0 = make_float2(siluf(as_[nt][0]), siluf(as_[nt][1]));
        float2 dv1 = make_float2(siluf(as_[nt][2]), siluf(as_[nt][3]));
        *reinterpret_cast<float2*>(&g_drive[(size_t)r0 * DD + gch])       = dv0;
        *reinterpret_cast<float2*>(&g_drive[(size_t)(r0 + 8) * DD + gch]) = dv1;
        float2 hv0 = make_float2(gn0 * siluf(ad_[nt][0]), gn1 * siluf(ad_[nt][1]));
        float2 hv1 = make_float2(gn0 * siluf(ad_[nt][2]), gn1 * siluf(ad_[nt][3]));
        *reinterpret_cast<float2*>(&g_hd[(size_t)r0 * DD + gch])       = hv0;
        *reinterpret_cast<float2*>(&g_hd[(size_t)(r0 + 8) * DD + gch]) = hv1;
    }
}

// ---------------- sA: per-chunk end-state with zero init ----------------
__global__ void __launch_bounds__(256) k_sA(const float* __restrict__ lAs,
                                            const float* __restrict__ ldts) {
    int c = blockIdx.x, b = blockIdx.y;
    int d0 = threadIdx.x * 4;
    float4 a = decay4(lAs, ldts, d0);
    float4 y = make_float4(0.f, 0.f, 0.f, 0.f);
    size_t base = ((size_t)(b * TT_SEQ + c * LC)) * DD + d0;
#pragma unroll 4
    for (int s = 0; s < LC; s++) {
        float4 dr = *reinterpret_cast<const float4*>(&g_drive[base + (size_t)s * DD]);
        y.x = fmaf(a.x, y.x, dr.x);
        y.y = fmaf(a.y, y.y, dr.y);
        y.z = fmaf(a.z, y.z, dr.z);
        y.w = fmaf(a.w, y.w, dr.w);
    }
    *reinterpret_cast<float4*>(&g_csum[((size_t)(b * NC + c)) * DD + d0]) = y;
}

// ---------------- s1b: cross-chunk carry scan ----------------
__global__ void __launch_bounds__(256) k_s1b(const float* __restrict__ lAs,
                                             const float* __restrict__ ldts) {
    int gt = blockIdx.x * blockDim.x + threadIdx.x;   // 0..BB*DD/4-1
    int b = gt >> 8;
    int d0 = (gt & 255) * 4;
    float4 a = decay4(lAs, ldts, d0);
    float4 aL;
    aL.x = __expf((float)LC * __logf(a.x));
    aL.y = __expf((float)LC * __logf(a.y));
    aL.z = __expf((float)LC * __logf(a.z));
    aL.w = __expf((float)LC * __logf(a.w));
    float4 carry = make_float4(0.f, 0.f, 0.f, 0.f);
#pragma unroll 8
    for (int c = 0; c < NC; c++) {
        size_t idx = ((size_t)(b * NC + c)) * DD + d0;
        *reinterpret_cast<float4*>(&g_carry[idx]) = carry;
        float4 cs = *reinterpret_cast<const float4*>(&g_csum[idx]);
        carry.x = fmaf(carry.x, aL.x, cs.x);
        carry.y = fmaf(carry.y, aL.y, cs.y);
        carry.z = fmaf(carry.z, aL.z, cs.z);
        carry.w = fmaf(carry.w, aL.w, cs.w);
    }
}

// ---------------- sB: fused scan (seeded with carry) + h_depth + RMS norm -> hn ----------------
__global__ void __launch_bounds__(256) k_sB(const float* __restrict__ lAs,
                                            const float* __restrict__ ldts) {
    int c = blockIdx.x, b = blockIdx.y;
    int tid = threadIdx.x, lane = tid & 31, wid = tid >> 5;
    int d0 = tid * 4;
    float4 a = decay4(lAs, ldts, d0);
    float4 y = *reinterpret_cast<const float4*>(&g_carry[((size_t)(b * NC + c)) * DD + d0]);
    __shared__ float red[2][8];
    size_t base = ((size_t)(b * TT_SEQ + c * LC)) * DD + d0;
    for (int s = 0; s < LC; s++) {
        size_t row = base + (size_t)s * DD;
        float4 dr = *reinterpret_cast<const float4*>(&g_drive[row]);
        float4 hd = *reinterpret_cast<const float4*>(&g_hd[row]);
        y.x = fmaf(a.x, y.x, dr.x);
        y.y = fmaf(a.y, y.y, dr.y);
        y.z = fmaf(a.z, y.z, dr.z);
        y.w = fmaf(a.w, y.w, dr.w);
        float4 h = make_float4(y.x + hd.x, y.y + hd.y, y.z + hd.z, y.w + hd.w);
        float ss = h.x * h.x + h.y * h.y + h.z * h.z + h.w * h.w;
#pragma unroll
        for (int off = 16; off > 0; off >>= 1) ss += __shfl_xor_sync(0xffffffffu, ss, off);
        if (lane == 0) red[s & 1][wid] = ss;
        __syncthreads();
        float tot = red[s & 1][0] + red[s & 1][1] + red[s & 1][2] + red[s & 1][3]
                  + red[s & 1][4] + red[s & 1][5] + red[s & 1][6] + red[s & 1][7];
        float rn = rsqrtf(tot * (1.0f / DD) + EPSV);
        float4 o = make_float4(h.x * rn, h.y * rn, h.z * rn, h.w * rn);
        *reinterpret_cast<float4*>(&g_hn[row]) = o;
    }
}

// ---------------- G2: r = silu(bd(concat[hn,e,shifted_e], w_post)) ----------------
__device__ __forceinline__ void stage_A_cat(unsigned* sA, int tok0, int gcat0, int tid) {
#pragma unroll
    for (int it = 0; it < 4; ++it) {
        int idx4 = tid + it * 256;
        int i  = idx4 >> 4;
        int j0 = (idx4 & 15) << 2;
        int gcat = gcat0 + j0;
        int tok = tok0 + i;
        float4 v;
        if (gcat < 1024) {
            v = *reinterpret_cast<const float4*>(&g_hn[(size_t)tok * DD + gcat]);
        } else if (gcat < 2048) {
            v = *reinterpret_cast<const float4*>(&g_e[(size_t)tok * DD + (gcat - 1024)]);
        } else {
            if ((tok & (TT_SEQ - 1)) == 0) v = make_float4(0.f, 0.f, 0.f, 0.f);
            else v = *reinterpret_cast<const float4*>(&g_e[(size_t)(tok - 1) * DD + (gcat - 2048)]);
        }
        int mt = i >> 4, rr = i & 15, half = rr >> 3, g = rr & 7;
        int ks = j0 >> 3, hi = (j0 >> 2) & 1;
        unsigned* p = &sA[(((mt * 8 + ks) * 32) + g * 4) * 4 + (half + 2 * hi)];
        p[0]  = f2tf(v.x);
        p[4]  = f2tf(v.y);
        p[8]  = f2tf(v.z);
        p[12] = f2tf(v.w);
    }
}

__global__ void __launch_bounds__(256) k_g2(const float* __restrict__ wpost) {
    __shared__ unsigned sA[4096];
    __shared__ unsigned sB[4096];
    int blk = blockIdx.y;
    int tok0 = blockIdx.x * 64;
    int tid = threadIdx.x, lane = tid & 31, w = tid >> 5, wm = w & 3, wn = w >> 2;
    float acc[4][4] = {};
#pragma unroll
    for (int kt = 0; kt < 3; ++kt) {
        stage_A_cat(sA, tok0, blk * BIP + kt * 64, tid);
        stage_B(sB, wpost + (size_t)blk * 64 * BIP + kt * 64, BIP, tid);
        __syncthreads();
        mma_chunk(acc, sA, sB, wm, wn, lane);
        __syncthreads();
    }
    int g = lane >> 2, t = lane & 3;
    int r0 = tok0 + wm * 16 + g;
#pragma unroll
    for (int nt = 0; nt < 4; nt++) {
        int n = blk * 64 + (wn * 4 + nt) * 8 + t * 2;
        float2 v0 = make_float2(siluf(acc[nt][0]), siluf(acc[nt][1]));
        float2 v1 = make_float2(siluf(acc[nt][2]), siluf(acc[nt][3]));
        *reinterpret_cast<float2*>(&g_r[(size_t)r0 * DD + n])       = v0;
        *reinterpret_cast<float2*>(&g_r[(size_t)(r0 + 8) * DD + n]) = v1;
    }
}

// ---------------- G3: t = r @ lr_B^T ----------------
__global__ void __launch_bounds__(256) k_g3(const float* __restrict__ lrB) {
    __shared__ unsigned sA[4096];
    __shared__ unsigned sB[4096];
    int tok0 = blockIdx.x * 64;
    int tid = threadIdx.x, lane = tid & 31, w = tid >> 5, wm = w & 3, wn = w >> 2;
    float acc[4][4] = {};
    for (int kt = 0; kt < 16; ++kt) {
        stage_A(sA, g_r + (size_t)tok0 * DD + kt * 64, DD, tid);
        stage_B(sB, lrB + kt * 64, DD, tid);
        __syncthreads();
        mma_chunk(acc, sA, sB, wm, wn, lane);
        __syncthreads();
    }
    int g = lane >> 2, t = lane & 3;
    int r0 = tok0 + wm * 16 + g;
#pragma unroll
    for (int nt = 0; nt < 4; nt++) {
        int n = (wn * 4 + nt) * 8 + t * 2;
        *reinterpret_cast<float2*>(&g_t[(size_t)r0 * RANKR + n]) =
            make_float2(acc[nt][0], acc[nt][1]);
        *reinterpret_cast<float2*>(&g_t[(size_t)(r0 + 8) * RANKR + n]) =
            make_float2(acc[nt][2], acc[nt][3]);
    }
}

// ---------------- G4: out = x + bd(r, w_local) + t @ lr_A^T ----------------
__global__ void __launch_bounds__(256) k_g4(const float* __restrict__ x,
                                            const float* __restrict__ wloc,
                                            const float* __restrict__ lrA,
                                            float* __restrict__ out) {
    __shared__ unsigned sA[4096];
    __shared__ unsigned sB[4096];
    int blk = blockIdx.y;
    int tok0 = blockIdx.x * 64;
    int tid = threadIdx.x, lane = tid & 31, w = tid >> 5, wm = w & 3, wn = w >> 2;
    float acc[4][4] = {};

    stage_A(sA, g_r + (size_t)tok0 * DD + blk * 64, DD, tid);
    stage_B(sB, wloc + (size_t)blk * 4096, 64, tid);
    __syncthreads();
    mma_chunk(acc, sA, sB, wm, wn, lane);
    __syncthreads();

    stage_A(sA, g_t + (size_t)tok0 * RANKR, RANKR, tid);
    stage_B(sB, lrA + (size_t)blk * 4096, 64, tid);
    __syncthreads();
    mma_chunk(acc, sA, sB, wm, wn, lane);

    int g = lane >> 2, t = lane & 3;
    int r0 = tok0 + wm * 16 + g;
#pragma unroll
    for (int nt = 0; nt < 4; nt++) {
        int n = blk * 64 + (wn * 4 + nt) * 8 + t * 2;
        size_t i0 = (size_t)r0 * DD + n;
        size_t i1 = (size_t)(r0 + 8) * DD + n;
        float2 x0 = *reinterpret_cast<const float2*>(&x[i0]);
        float2 x1 = *reinterpret_cast<const float2*>(&x[i1]);
        *reinterpret_cast<float2*>(&out[i0]) = make_float2(x0.x + acc[nt][0], x0.y + acc[nt][1]);
        *reinterpret_cast<float2*>(&out[i1]) = make_float2(x1.x + acc[nt][2], x1.y + acc[nt][3]);
    }
}

// ---------------- launch ----------------
extern "C" void kernel_launch(void* const* d_in, const int* in_sizes, int n_in,
                              void* d_out, int out_size) {
    const float* x    = (const float*)d_in[0];
    const int*   actk = (const int*)  d_in[1];
    const float* wseq = (const float*)d_in[2];
    const float* wdep = (const float*)d_in[3];
    const float* wpost= (const float*)d_in[4];
    const float* wloc = (const float*)d_in[5];
    const float* lrA  = (const float*)d_in[6];
    const float* lrB  = (const float*)d_in[7];
    const float* lAs  = (const float*)d_in[8];
    const float* ldts = (const float*)d_in[9];
    const float* lAd  = (const float*)d_in[10];
    const float* ldtd = (const float*)d_in[11];
    float* out = (float*)d_out;

    float* e_ptr; cudaGetSymbolAddress((void**)&e_ptr, g_e);

    dim3 gGemm(NTOK / 64, NBLK);     // (256, 16)
    dim3 gScan(NC, BB);              // (64, 4)

    k_rmsnorm<<<NTOK, 256>>>(x, e_ptr);
    k_g1<<<gGemm, 256>>>(wseq, wdep, lAd, ldtd, actk);
    k_sA<<<gScan, 256>>>(lAs, ldts);
    k_s1b<<<(BB * DD / 4) / 256, 256>>>(lAs, ldts);
    k_sB<<<gScan, 256>>>(lAs, ldts);
    k_g2<<<gGemm, 256>>>(wpost);
    k_g3<<<NTOK / 64, 256>>>(lrB);
    k_g4<<<gGemm, 256>>>(x, wloc, lrA, out);
}

// round 3
// speedup vs baseline: 2.3950x; 1.0881x over previous
#include <cuda_runtime.h>
#include <math.h>

// ---------------- problem constants ----------------
#define BB 4
#define TT_SEQ 4096
#define DD 1024
#define NTOK (BB*TT_SEQ)          // 16384
#define NBLK 16
#define BIP 192                   // w_post block input width
#define RANKR 64
#define NMEM 128
#define LC 64                     // scan chunk length (== GEMM token tile)
#define NC (TT_SEQ/LC)            // 64 chunks
#define EPSV 1.1920929e-07f

// ---------------- scratch (device globals; no allocation) ----------------
__device__ float g_drive[NTOK*DD];
__device__ float g_hd   [NTOK*DD];
__device__ float g_hn   [NTOK*DD];   // UNNORMALIZED h
__device__ float g_r    [NTOK*DD];
__device__ float g_t    [NTOK*RANKR];
__device__ float g_csum [BB*NC*DD];
__device__ float g_sspart[NTOK*8];
__device__ float g_rsx  [NTOK];      // rsqrt stats of x
__device__ float g_rsh  [NTOK];      // rsqrt stats of h

__device__ __forceinline__ float siluf(float x) {
    return x / (1.0f + __expf(-x));
}

__device__ __forceinline__ unsigned f2tf(float f) {
    unsigned u;
    asm("cvt.rna.tf32.f32 %0, %1;" : "=r"(u) : "f"(f));
    return u;
}

__device__ __forceinline__ float decay1(const float* __restrict__ lA,
                                        const float* __restrict__ ldt, int d) {
    return fmaxf(__expf(-__expf(lA[d]) * __expf(ldt[d])), 1e-6f);
}

__device__ __forceinline__ float4 decay4(const float* __restrict__ lA,
                                         const float* __restrict__ ldt, int d0) {
    float4 r;
    r.x = decay1(lA, ldt, d0 + 0);
    r.y = decay1(lA, ldt, d0 + 1);
    r.z = decay1(lA, ldt, d0 + 2);
    r.w = decay1(lA, ldt, d0 + 3);
    return r;
}

// ---------------- tf32 MMA machinery ----------------
// CTA = 256 threads = 8 warps. Tile M=64 x N=64, K in 64-chunks.
// Warp w: wm = w&3 (m16 tile), wn = w>>2 (n32 half), 4 n8 subtiles.
// smem fragment-major: A frag = LDS.128, B frag = LDS.64, conflict-free.

__device__ __forceinline__ void mma_tf32(float c[4], const unsigned a[4], const unsigned b[2]) {
    asm volatile("mma.sync.aligned.m16n8k8.row.col.f32.tf32.tf32.f32 "
        "{%0,%1,%2,%3}, {%4,%5,%6,%7}, {%8,%9}, {%0,%1,%2,%3};"
        : "+f"(c[0]), "+f"(c[1]), "+f"(c[2]), "+f"(c[3])
        : "r"(a[0]), "r"(a[1]), "r"(a[2]), "r"(a[3]), "r"(b[0]), "r"(b[1]));
}

__device__ __forceinline__ void put_A(unsigned* sA, int i, int j0, float4 v) {
    int mt = i >> 4, rr = i & 15, half = rr >> 3, g = rr & 7;
    int ks = j0 >> 3, hi = (j0 >> 2) & 1;
    unsigned* p = &sA[(((mt * 8 + ks) * 32) + g * 4) * 4 + (half + 2 * hi)];
    p[0]  = f2tf(v.x);
    p[4]  = f2tf(v.y);
    p[8]  = f2tf(v.z);
    p[12] = f2tf(v.w);
}

// stage 64x64 A tile from row-major source
__device__ __forceinline__ void stage_A(unsigned* sA, const float* __restrict__ base,
                                        int rs, int tid) {
#pragma unroll
    for (int it = 0; it < 4; ++it) {
        int idx4 = tid + it * 256;
        int i  = idx4 >> 4;
        int j0 = (idx4 & 15) << 2;
        float4 v = *reinterpret_cast<const float4*>(base + (size_t)i * rs + j0);
        put_A(sA, i, j0, v);
    }
}

// stage A from x with per-row scale (fused rms norm)
__device__ __forceinline__ void stage_A_scaled(unsigned* sA, const float* __restrict__ base,
                                               const float* __restrict__ scale,
                                               int tok0, int rs, int tid) {
#pragma unroll
    for (int it = 0; it < 4; ++it) {
        int idx4 = tid + it * 256;
        int i  = idx4 >> 4;
        int j0 = (idx4 & 15) << 2;
        float4 v = *reinterpret_cast<const float4*>(base + (size_t)i * rs + j0);
        float sc = scale[tok0 + i];
        v.x *= sc; v.y *= sc; v.z *= sc; v.w *= sc;
        put_A(sA, i, j0, v);
    }
}

// stage 64x64 B tile: rows = outputs n, k contiguous, stride rs
__device__ __forceinline__ void stage_B(unsigned* sB, const float* __restrict__ base,
                                        int rs, int tid) {
#pragma unroll
    for (int it = 0; it < 4; ++it) {
        int idx4 = tid + it * 256;
        int n  = idx4 >> 4;
        int k0 = (idx4 & 15) << 2;
        float4 v = *reinterpret_cast<const float4*>(base + (size_t)n * rs + k0);
        int nt = n >> 3, g = n & 7;
        int ks = k0 >> 3, hi = (k0 >> 2) & 1;
        unsigned* p = &sB[(((nt * 8 + ks) * 32) + g * 4) * 2 + hi];
        p[0] = f2tf(v.x);
        p[2] = f2tf(v.y);
        p[4] = f2tf(v.z);
        p[6] = f2tf(v.w);
    }
}

__device__ __forceinline__ void mma_chunk(float acc[4][4], const unsigned* sA,
                                          const unsigned* sB, int wm, int wn, int lane) {
#pragma unroll
    for (int ks = 0; ks < 8; ks++) {
        unsigned a[4];
        *reinterpret_cast<uint4*>(a) =
            *reinterpret_cast<const uint4*>(&sA[((wm * 8 + ks) * 32 + lane) * 4]);
#pragma unroll
        for (int nt = 0; nt < 4; nt++) {
            unsigned b[2];
            *reinterpret_cast<uint2*>(b) =
                *reinterpret_cast<const uint2*>(&sB[(((wn * 4 + nt) * 8 + ks) * 32 + lane) * 2]);
            mma_tf32(acc[nt], a, b);
        }
    }
}

// ---------------- stats: g_rsx[tok] = rsqrt(mean(x^2)+eps) ----------------
__global__ void __launch_bounds__(256) k_stats(const float* __restrict__ x) {
    int w = threadIdx.x >> 5, lane = threadIdx.x & 31;
    int tok = blockIdx.x * 8 + w;
    const float4* xr = reinterpret_cast<const float4*>(x + (size_t)tok * DD);
    float ss = 0.0f;
#pragma unroll
    for (int i = 0; i < 8; i++) {
        float4 v = xr[lane + i * 32];
        ss += v.x * v.x + v.y * v.y + v.z * v.z + v.w * v.w;
    }
#pragma unroll
    for (int off = 16; off > 0; off >>= 1) ss += __shfl_xor_sync(0xffffffffu, ss, off);
    if (lane == 0) g_rsx[tok] = rsqrtf(ss * (1.0f / DD) + EPSV);
}

// ---------------- gain helper ----------------
__device__ __forceinline__ float gain_of(int gch, float Kf, const float* __restrict__ lAd,
                                         const float* __restrict__ ldtd) {
    if (gch < NMEM) return Kf;
    float a1 = __expf(-__expf(lAd[gch - NMEM]) * __expf(ldtd[gch - NMEM]));
    float om = 1.0f - a1;
    if (fabsf(om) < 1e-6f) return Kf;
    return (1.0f - __expf(Kf * __logf(a1))) / fmaxf(om, 1e-8f);
}

// ---------------- G1: drive/hd GEMMs + fused per-chunk scan -> g_csum ----------------
__global__ void __launch_bounds__(256) k_g1(const float* __restrict__ x,
                                            const float* __restrict__ wseq,
                                            const float* __restrict__ wdep,
                                            const float* __restrict__ lAd,
                                            const float* __restrict__ ldtd,
                                            const float* __restrict__ lAs,
                                            const float* __restrict__ ldts,
                                            const int* __restrict__ kptr) {
    __shared__ unsigned sA[4096];
    __shared__ unsigned sBB[8192];          // B1 | B2, later reused as drive tile
    int blk = blockIdx.y;
    int tok0 = blockIdx.x * 64;
    int tid = threadIdx.x, lane = tid & 31, w = tid >> 5, wm = w & 3, wn = w >> 2;

    stage_A_scaled(sA, x + (size_t)tok0 * DD + blk * 64, g_rsx, tok0, DD, tid);
    stage_B(sBB, wseq + (size_t)blk * 4096, 64, tid);
    stage_B(sBB + 4096, wdep + (size_t)blk * 4096, 64, tid);
    __syncthreads();

    float as_[4][4] = {}, ad_[4][4] = {};
#pragma unroll
    for (int ks = 0; ks < 8; ks++) {
        unsigned a[4];
        *reinterpret_cast<uint4*>(a) =
            *reinterpret_cast<const uint4*>(&sA[((wm * 8 + ks) * 32 + lane) * 4]);
#pragma unroll
        for (int nt = 0; nt < 4; nt++) {
            unsigned b[2];
            int off = (((wn * 4 + nt) * 8 + ks) * 32 + lane) * 2;
            *reinterpret_cast<uint2*>(b) = *reinterpret_cast<const uint2*>(&sBB[off]);
            mma_tf32(as_[nt], a, b);
            *reinterpret_cast<uint2*>(b) = *reinterpret_cast<const uint2*>(&sBB[4096 + off]);
            mma_tf32(ad_[nt], a, b);
        }
    }
    __syncthreads();                 // B tiles dead; reuse sBB as drive scratch

    float* sD = reinterpret_cast<float*>(sBB);   // [64 rows][stride 65]
    float Kf = (float)(*kptr);
    int g = lane >> 2, t = lane & 3;
    int rl0 = wm * 16 + g;
    int r0 = tok0 + rl0;
#pragma unroll
    for (int nt = 0; nt < 4; nt++) {
        int nl = (wn * 4 + nt) * 8 + t * 2;
        int gch = blk * 64 + nl;
        float gn0 = gain_of(gch, Kf, lAd, ldtd);
        float gn1 = gain_of(gch + 1, Kf, lAd, ldtd);
        float d0 = siluf(as_[nt][0]), d1 = siluf(as_[nt][1]);
        float d2 = siluf(as_[nt][2]), d3 = siluf(as_[nt][3]);
        *reinterpret_cast<float2*>(&g_drive[(size_t)r0 * DD + gch])       = make_float2(d0, d1);
        *reinterpret_cast<float2*>(&g_drive[(size_t)(r0 + 8) * DD + gch]) = make_float2(d2, d3);
        sD[rl0 * 65 + nl]       = d0;
        sD[rl0 * 65 + nl + 1]   = d1;
        sD[(rl0 + 8) * 65 + nl]     = d2;
        sD[(rl0 + 8) * 65 + nl + 1] = d3;
        *reinterpret_cast<float2*>(&g_hd[(size_t)r0 * DD + gch]) =
            make_float2(gn0 * siluf(ad_[nt][0]), gn1 * siluf(ad_[nt][1]));
        *reinterpret_cast<float2*>(&g_hd[(size_t)(r0 + 8) * DD + gch]) =
            make_float2(gn0 * siluf(ad_[nt][2]), gn1 * siluf(ad_[nt][3]));
    }
    __syncthreads();

    // fused local chunk scan: this token tile IS scan chunk (b, c)
    if (tid < 64) {
        int gch = blk * 64 + tid;
        float a = decay1(lAs, ldts, gch);
        float y = 0.0f;
#pragma unroll
        for (int s = 0; s < LC; s++)
            y = fmaf(a, y, sD[s * 65 + tid]);
        int b = tok0 >> 12;
        int c = (tok0 >> 6) & (NC - 1);
        g_csum[((size_t)(b * NC + c)) * DD + gch] = y;
    }
}

// ---------------- sB: inline carry + scan + h store + rms partials ----------------
__global__ void __launch_bounds__(256) k_sB(const float* __restrict__ lAs,
                                            const float* __restrict__ ldts) {
    int c = blockIdx.x, b = blockIdx.y;
    int tid = threadIdx.x, lane = tid & 31, w = tid >> 5;
    int d0 = tid * 4;
    float4 a = decay4(lAs, ldts, d0);
    float4 aL;
    aL.x = __expf((float)LC * __logf(a.x));
    aL.y = __expf((float)LC * __logf(a.y));
    aL.z = __expf((float)LC * __logf(a.z));
    aL.w = __expf((float)LC * __logf(a.w));

    // carry prefix over earlier chunks (csum is small; L2-resident)
    float4 y = make_float4(0.f, 0.f, 0.f, 0.f);
    size_t csbase = (size_t)b * NC * DD + d0;
    for (int cp = 0; cp < c; cp++) {
        float4 cs = *reinterpret_cast<const float4*>(&g_csum[csbase + (size_t)cp * DD]);
        y.x = fmaf(y.x, aL.x, cs.x);
        y.y = fmaf(y.y, aL.y, cs.y);
        y.z = fmaf(y.z, aL.z, cs.z);
        y.w = fmaf(y.w, aL.w, cs.w);
    }

    int tokbase = b * TT_SEQ + c * LC;
    size_t base = (size_t)tokbase * DD + d0;
#pragma unroll 4
    for (int s = 0; s < LC; s++) {
        size_t row = base + (size_t)s * DD;
        float4 dr = *reinterpret_cast<const float4*>(&g_drive[row]);
        float4 hd = *reinterpret_cast<const float4*>(&g_hd[row]);
        y.x = fmaf(a.x, y.x, dr.x);
        y.y = fmaf(a.y, y.y, dr.y);
        y.z = fmaf(a.z, y.z, dr.z);
        y.w = fmaf(a.w, y.w, dr.w);
        float4 h = make_float4(y.x + hd.x, y.y + hd.y, y.z + hd.z, y.w + hd.w);
        *reinterpret_cast<float4*>(&g_hn[row]) = h;
        float ss = h.x * h.x + h.y * h.y + h.z * h.z + h.w * h.w;
#pragma unroll
        for (int off = 16; off > 0; off >>= 1) ss += __shfl_xor_sync(0xffffffffu, ss, off);
        if (lane == 0) g_sspart[(size_t)(tokbase + s) * 8 + w] = ss;
    }
}

// ---------------- rstd for h ----------------
__global__ void __launch_bounds__(256) k_rstd() {
    int tok = blockIdx.x * 256 + threadIdx.x;
    const float4* p = reinterpret_cast<const float4*>(&g_sspart[(size_t)tok * 8]);
    float4 a = p[0], b = p[1];
    float s = a.x + a.y + a.z + a.w + b.x + b.y + b.z + b.w;
    g_rsh[tok] = rsqrtf(s * (1.0f / DD) + EPSV);
}

// ---------------- G2: r = silu(bd(concat[hn*rsh, x*rsx, shift(x*rsx)], w_post)) ----------------
__device__ __forceinline__ void stage_A_cat(unsigned* sA, const float* __restrict__ x,
                                            int tok0, int gcat0, int tid) {
#pragma unroll
    for (int it = 0; it < 4; ++it) {
        int idx4 = tid + it * 256;
        int i  = idx4 >> 4;
        int j0 = (idx4 & 15) << 2;
        int gcat = gcat0 + j0;
        int tok = tok0 + i;
        float4 v;
        float sc;
        if (gcat < 1024) {
            v = *reinterpret_cast<const float4*>(&g_hn[(size_t)tok * DD + gcat]);
            sc = g_rsh[tok];
        } else if (gcat < 2048) {
            v = *reinterpret_cast<const float4*>(&x[(size_t)tok * DD + (gcat - 1024)]);
            sc = g_rsx[tok];
        } else {
            if ((tok & (TT_SEQ - 1)) == 0) { v = make_float4(0.f, 0.f, 0.f, 0.f); sc = 0.0f; }
            else {
                v = *reinterpret_cast<const float4*>(&x[(size_t)(tok - 1) * DD + (gcat - 2048)]);
                sc = g_rsx[tok - 1];
            }
        }
        v.x *= sc; v.y *= sc; v.z *= sc; v.w *= sc;
        put_A(sA, i, j0, v);
    }
}

__global__ void __launch_bounds__(256) k_g2(const float* __restrict__ x,
                                            const float* __restrict__ wpost) {
    __shared__ unsigned sA[4096];
    __shared__ unsigned sB[4096];
    int blk = blockIdx.y;
    int tok0 = blockIdx.x * 64;
    int tid = threadIdx.x, lane = tid & 31, w = tid >> 5, wm = w & 3, wn = w >> 2;
    float acc[4][4] = {};
#pragma unroll
    for (int kt = 0; kt < 3; ++kt) {
        stage_A_cat(sA, x, tok0, blk * BIP + kt * 64, tid);
        stage_B(sB, wpost + (size_t)blk * 64 * BIP + kt * 64, BIP, tid);
        __syncthreads();
        mma_chunk(acc, sA, sB, wm, wn, lane);
        __syncthreads();
    }
    int g = lane >> 2, t = lane & 3;
    int r0 = tok0 + wm * 16 + g;
#pragma unroll
    for (int nt = 0; nt < 4; nt++) {
        int n = blk * 64 + (wn * 4 + nt) * 8 + t * 2;
        *reinterpret_cast<float2*>(&g_r[(size_t)r0 * DD + n]) =
            make_float2(siluf(acc[nt][0]), siluf(acc[nt][1]));
        *reinterpret_cast<float2*>(&g_r[(size_t)(r0 + 8) * DD + n]) =
            make_float2(siluf(acc[nt][2]), siluf(acc[nt][3]));
    }
}

// ---------------- G3: t = r @ lr_B^T ----------------
__global__ void __launch_bounds__(256) k_g3(const float* __restrict__ lrB) {
    __shared__ unsigned sA[4096];
    __shared__ unsigned sB[4096];
    int tok0 = blockIdx.x * 64;
    int tid = threadIdx.x, lane = tid & 31, w = tid >> 5, wm = w & 3, wn = w >> 2;
    float acc[4][4] = {};
    for (int kt = 0; kt < 16; ++kt) {
        stage_A(sA, g_r + (size_t)tok0 * DD + kt * 64, DD, tid);
        stage_B(sB, lrB + kt * 64, DD, tid);
        __syncthreads();
        mma_chunk(acc, sA, sB, wm, wn, lane);
        __syncthreads();
    }
    int g = lane >> 2, t = lane & 3;
    int r0 = tok0 + wm * 16 + g;
#pragma unroll
    for (int nt = 0; nt < 4; nt++) {
        int n = (wn * 4 + nt) * 8 + t * 2;
        *reinterpret_cast<float2*>(&g_t[(size_t)r0 * RANKR + n]) =
            make_float2(acc[nt][0], acc[nt][1]);
        *reinterpret_cast<float2*>(&g_t[(size_t)(r0 + 8) * RANKR + n]) =
            make_float2(acc[nt][2], acc[nt][3]);
    }
}

// ---------------- G4: out = x + bd(r, w_local) + t @ lr_A^T ----------------
__global__ void __launch_bounds__(256) k_g4(const float* __restrict__ x,
                                            const float* __restrict__ wloc,
                                            const float* __restrict__ lrA,
                                            float* __restrict__ out) {
    __shared__ unsigned sA[4096];
    __shared__ unsigned sB[4096];
    int blk = blockIdx.y;
    int tok0 = blockIdx.x * 64;
    int tid = threadIdx.x, lane = tid & 31, w = tid >> 5, wm = w & 3, wn = w >> 2;
    float acc[4][4] = {};

    stage_A(sA, g_r + (size_t)tok0 * DD + blk * 64, DD, tid);
    stage_B(sB, wloc + (size_t)blk * 4096, 64, tid);
    __syncthreads();
    mma_chunk(acc, sA, sB, wm, wn, lane);
    __syncthreads();

    stage_A(sA, g_t + (size_t)tok0 * RANKR, RANKR, tid);
    stage_B(sB, lrA + (size_t)blk * 4096, 64, tid);
    __syncthreads();
    mma_chunk(acc, sA, sB, wm, wn, lane);

    int g = lane >> 2, t = lane & 3;
    int r0 = tok0 + wm * 16 + g;
#pragma unroll
    for (int nt = 0; nt < 4; nt++) {
        int n = blk * 64 + (wn * 4 + nt) * 8 + t * 2;
        size_t i0 = (size_t)r0 * DD + n;
        size_t i1 = (size_t)(r0 + 8) * DD + n;
        float2 x0 = *reinterpret_cast<const float2*>(&x[i0]);
        float2 x1 = *reinterpret_cast<const float2*>(&x[i1]);
        *reinterpret_cast<float2*>(&out[i0]) = make_float2(x0.x + acc[nt][0], x0.y + acc[nt][1]);
        *reinterpret_cast<float2*>(&out[i1]) = make_float2(x1.x + acc[nt][2], x1.y + acc[nt][3]);
    }
}

// ---------------- launch ----------------
extern "C" void kernel_launch(void* const* d_in, const int* in_sizes, int n_in,
                              void* d_out, int out_size) {
    const float* x    = (const float*)d_in[0];
    const int*   actk = (const int*)  d_in[1];
    const float* wseq = (const float*)d_in[2];
    const float* wdep = (const float*)d_in[3];
    const float* wpost= (const float*)d_in[4];
    const float* wloc = (const float*)d_in[5];
    const float* lrA  = (const float*)d_in[6];
    const float* lrB  = (const float*)d_in[7];
    const float* lAs  = (const float*)d_in[8];
    const float* ldts = (const float*)d_in[9];
    const float* lAd  = (const float*)d_in[10];
    const float* ldtd = (const float*)d_in[11];
    float* out = (float*)d_out;

    dim3 gGemm(NTOK / 64, NBLK);     // (256, 16)
    dim3 gScan(NC, BB);              // (64, 4)

    k_stats<<<NTOK / 8, 256>>>(x);
    k_g1<<<gGemm, 256>>>(x, wseq, wdep, lAd, ldtd, lAs, ldts, actk);
    k_sB<<<gScan, 256>>>(lAs, ldts);
    k_rstd<<<NTOK / 256, 256>>>();
    k_g2<<<gGemm, 256>>>(x, wpost);
    k_g3<<<NTOK / 64, 256>>>(lrB);
    k_g4<<<gGemm, 256>>>(x, wloc, lrA, out);
}

// round 4
// speedup vs baseline: 4.2610x; 1.7791x over previous
#include <cuda_runtime.h>
#include <cuda_bf16.h>
#include <math.h>

// ---------------- problem constants ----------------
#define BB 4
#define TT_SEQ 4096
#define DD 1024
#define NTOK (BB*TT_SEQ)          // 16384
#define NBLK 16
#define BIP 192                   // w_post block input width
#define RANKR 64
#define NMEM 128
#define LC 64                     // scan chunk length (== GEMM token tile)
#define NC (TT_SEQ/LC)            // 64 chunks
#define EPSV 1.1920929e-07f

// smem fragment-slot strides (padded to reduce STS bank conflicts)
#define ASLOT 132                 // uints per (mt,ks) A slot: 32 lanes * 4 regs + pad
#define BSLOT 66                  // uints per (nt,ks) B slot: 32 lanes * 2 regs + pad
#define ASZ (16*ASLOT)            // 2112 uints
#define BSZ (32*BSLOT)            // 2112 uints

// ---------------- scratch (device globals; no allocation) ----------------
__device__ __nv_bfloat16 g_drive[NTOK*DD];
__device__ __nv_bfloat16 g_hd   [NTOK*DD];
__device__ __nv_bfloat16 g_hn   [NTOK*DD];   // UNNORMALIZED h
__device__ __nv_bfloat16 g_r    [NTOK*DD];
__device__ float g_t    [NTOK*RANKR];
__device__ float g_csum [BB*NC*DD];
__device__ float g_sspart[NTOK*8];
__device__ float g_rsx  [NTOK];
__device__ float g_rsh  [NTOK];

__device__ __forceinline__ float siluf(float x) {
    return x / (1.0f + __expf(-x));
}

// pack two fp32 -> bf16x2 (lo = a, hi = b)
__device__ __forceinline__ unsigned pk(float a, float b) {
    unsigned r;
    asm("cvt.rn.bf16x2.f32 %0, %1, %2;" : "=r"(r) : "f"(b), "f"(a));
    return r;
}

__device__ __forceinline__ float decay1(const float* __restrict__ lA,
                                        const float* __restrict__ ldt, int d) {
    return fmaxf(__expf(-__expf(lA[d]) * __expf(ldt[d])), 1e-6f);
}

__device__ __forceinline__ float4 decay4(const float* __restrict__ lA,
                                         const float* __restrict__ ldt, int d0) {
    float4 r;
    r.x = decay1(lA, ldt, d0 + 0);
    r.y = decay1(lA, ldt, d0 + 1);
    r.z = decay1(lA, ldt, d0 + 2);
    r.w = decay1(lA, ldt, d0 + 3);
    return r;
}

// ---------------- bf16 MMA machinery ----------------
// CTA = 256 threads = 8 warps. Tile M=64 x N=64, K in 64-chunks (4 x k16).
// Warp w: wm = w&3 (m16 tile), wn = w>>2 (n32 half), 4 n8 subtiles.
// smem fragment-major: A frag = 1 LDS.128 (4 regs), B frag = 1 LDS.64 (2 regs).

__device__ __forceinline__ void mma_bf16(float c[4], const unsigned a[4], const unsigned b[2]) {
    asm volatile("mma.sync.aligned.m16n8k16.row.col.f32.bf16.bf16.f32 "
        "{%0,%1,%2,%3}, {%4,%5,%6,%7}, {%8,%9}, {%0,%1,%2,%3};"
        : "+f"(c[0]), "+f"(c[1]), "+f"(c[2]), "+f"(c[3])
        : "r"(a[0]), "r"(a[1]), "r"(a[2]), "r"(a[3]), "r"(b[0]), "r"(b[1]));
}

// place 4 consecutive-k fp32 values for A row i, col j0 (j0 % 4 == 0)
__device__ __forceinline__ void put_A4(unsigned* sA, int i, int j0, float4 v) {
    int mt = i >> 4, rr = i & 15, half = rr >> 3, g = rr & 7;
    int ks = j0 >> 4, kk = j0 & 15, hi = kk >> 3, t0 = (kk & 7) >> 1;
    unsigned* p = &sA[(mt * 4 + ks) * ASLOT + (g * 4 + t0) * 4 + half + 2 * hi];
    p[0] = pk(v.x, v.y);
    p[4] = pk(v.z, v.w);
}

// stage 64x64 A tile from fp32 row-major source, optional per-row scale
template<bool SCALED>
__device__ __forceinline__ void stageA32(unsigned* sA, const float* __restrict__ base,
                                         const float* __restrict__ scale, int tok0,
                                         int rs, int tid) {
#pragma unroll
    for (int it = 0; it < 4; ++it) {
        int idx = tid + it * 256;
        int i  = idx >> 4;
        int j0 = (idx & 15) << 2;
        float4 v = *reinterpret_cast<const float4*>(base + (size_t)i * rs + j0);
        if (SCALED) {
            float sc = scale[tok0 + i];
            v.x *= sc; v.y *= sc; v.z *= sc; v.w *= sc;
        }
        put_A4(sA, i, j0, v);
    }
}

// stage 64x64 A tile from bf16 row-major source (no scale) — passthrough packing
__device__ __forceinline__ void stageA16(unsigned* sA, const __nv_bfloat16* __restrict__ base,
                                         int rs, int tid) {
#pragma unroll
    for (int it = 0; it < 4; ++it) {
        int idx = tid + it * 256;
        int i  = idx >> 4;
        int j0 = (idx & 15) << 2;
        uint2 u = *reinterpret_cast<const uint2*>(base + (size_t)i * rs + j0);
        int mt = i >> 4, rr = i & 15, half = rr >> 3, g = rr & 7;
        int ks = j0 >> 4, kk = j0 & 15, hi = kk >> 3, t0 = (kk & 7) >> 1;
        unsigned* p = &sA[(mt * 4 + ks) * ASLOT + (g * 4 + t0) * 4 + half + 2 * hi];
        p[0] = u.x;
        p[4] = u.y;
    }
}

// stage 64x64 B tile from fp32 (rows = outputs n, k contiguous, stride rs)
__device__ __forceinline__ void stage_B(unsigned* sB, const float* __restrict__ base,
                                        int rs, int tid) {
#pragma unroll
    for (int it = 0; it < 4; ++it) {
        int idx = tid + it * 256;
        int n  = idx >> 4;
        int k0 = (idx & 15) << 2;
        float4 v = *reinterpret_cast<const float4*>(base + (size_t)n * rs + k0);
        int nt = n >> 3, g = n & 7;
        int ks = k0 >> 4, kk = k0 & 15, hi = kk >> 3, t0 = (kk & 7) >> 1;
        unsigned* p = &sB[(nt * 4 + ks) * BSLOT + (g * 4 + t0) * 2 + hi];
        p[0] = pk(v.x, v.y);
        p[2] = pk(v.z, v.w);
    }
}

__device__ __forceinline__ void mma_chunk(float acc[4][4], const unsigned* sA,
                                          const unsigned* sB, int wm, int wn, int lane) {
#pragma unroll
    for (int ks = 0; ks < 4; ks++) {
        unsigned a[4];
        *reinterpret_cast<uint4*>(a) =
            *reinterpret_cast<const uint4*>(&sA[(wm * 4 + ks) * ASLOT + lane * 4]);
#pragma unroll
        for (int nt = 0; nt < 4; nt++) {
            unsigned b[2];
            *reinterpret_cast<uint2*>(b) =
                *reinterpret_cast<const uint2*>(&sB[((wn * 4 + nt) * 4 + ks) * BSLOT + lane * 2]);
            mma_bf16(acc[nt], a, b);
        }
    }
}

// ---------------- stats: g_rsx[tok] = rsqrt(mean(x^2)+eps) ----------------
__global__ void __launch_bounds__(256) k_stats(const float* __restrict__ x) {
    int w = threadIdx.x >> 5, lane = threadIdx.x & 31;
    int tok = blockIdx.x * 8 + w;
    const float4* xr = reinterpret_cast<const float4*>(x + (size_t)tok * DD);
    float ss = 0.0f;
#pragma unroll
    for (int i = 0; i < 8; i++) {
        float4 v = xr[lane + i * 32];
        ss += v.x * v.x + v.y * v.y + v.z * v.z + v.w * v.w;
    }
#pragma unroll
    for (int off = 16; off > 0; off >>= 1) ss += __shfl_xor_sync(0xffffffffu, ss, off);
    if (lane == 0) g_rsx[tok] = rsqrtf(ss * (1.0f / DD) + EPSV);
}

// ---------------- gain helper ----------------
__device__ __forceinline__ float gain_of(int gch, float Kf, const float* __restrict__ lAd,
                                         const float* __restrict__ ldtd) {
    if (gch < NMEM) return Kf;
    float a1 = __expf(-__expf(lAd[gch - NMEM]) * __expf(ldtd[gch - NMEM]));
    float om = 1.0f - a1;
    if (fabsf(om) < 1e-6f) return Kf;
    return (1.0f - __expf(Kf * __logf(a1))) / fmaxf(om, 1e-8f);
}

// ---------------- G1: drive/hd GEMMs + fused per-chunk scan -> g_csum ----------------
__global__ void __launch_bounds__(256) k_g1(const float* __restrict__ x,
                                            const float* __restrict__ wseq,
                                            const float* __restrict__ wdep,
                                            const float* __restrict__ lAd,
                                            const float* __restrict__ ldtd,
                                            const float* __restrict__ lAs,
                                            const float* __restrict__ ldts,
                                            const int* __restrict__ kptr) {
    __shared__ unsigned sA[ASZ];
    __shared__ unsigned sBB[2 * BSZ];       // B1 | B2; later reused as fp32 drive tile
    int blk = blockIdx.y;
    int tok0 = blockIdx.x * 64;
    int tid = threadIdx.x, lane = tid & 31, w = tid >> 5, wm = w & 3, wn = w >> 2;

    stageA32<true>(sA, x + (size_t)tok0 * DD + blk * 64, g_rsx, tok0, DD, tid);
    stage_B(sBB, wseq + (size_t)blk * 4096, 64, tid);
    stage_B(sBB + BSZ, wdep + (size_t)blk * 4096, 64, tid);
    __syncthreads();

    float as_[4][4] = {}, ad_[4][4] = {};
#pragma unroll
    for (int ks = 0; ks < 4; ks++) {
        unsigned a[4];
        *reinterpret_cast<uint4*>(a) =
            *reinterpret_cast<const uint4*>(&sA[(wm * 4 + ks) * ASLOT + lane * 4]);
#pragma unroll
        for (int nt = 0; nt < 4; nt++) {
            int off = ((wn * 4 + nt) * 4 + ks) * BSLOT + lane * 2;
            unsigned b[2];
            *reinterpret_cast<uint2*>(b) = *reinterpret_cast<const uint2*>(&sBB[off]);
            mma_bf16(as_[nt], a, b);
            *reinterpret_cast<uint2*>(b) = *reinterpret_cast<const uint2*>(&sBB[BSZ + off]);
            mma_bf16(ad_[nt], a, b);
        }
    }
    __syncthreads();                 // B tiles dead; reuse sBB as drive scratch

    float* sD = reinterpret_cast<float*>(sBB);   // [64 rows][stride 66]
    float Kf = (float)(*kptr);
    int g = lane >> 2, t = lane & 3;
    int rl0 = wm * 16 + g;
    int r0 = tok0 + rl0;
#pragma unroll
    for (int nt = 0; nt < 4; nt++) {
        int nl = (wn * 4 + nt) * 8 + t * 2;
        int gch = blk * 64 + nl;
        float gn0 = gain_of(gch, Kf, lAd, ldtd);
        float gn1 = gain_of(gch + 1, Kf, lAd, ldtd);
        float d0 = siluf(as_[nt][0]), d1 = siluf(as_[nt][1]);
        float d2 = siluf(as_[nt][2]), d3 = siluf(as_[nt][3]);
        *reinterpret_cast<unsigned*>(&g_drive[(size_t)r0 * DD + gch])       = pk(d0, d1);
        *reinterpret_cast<unsigned*>(&g_drive[(size_t)(r0 + 8) * DD + gch]) = pk(d2, d3);
        sD[rl0 * 66 + nl]         = d0;
        sD[rl0 * 66 + nl + 1]     = d1;
        sD[(rl0 + 8) * 66 + nl]     = d2;
        sD[(rl0 + 8) * 66 + nl + 1] = d3;
        *reinterpret_cast<unsigned*>(&g_hd[(size_t)r0 * DD + gch]) =
            pk(gn0 * siluf(ad_[nt][0]), gn1 * siluf(ad_[nt][1]));
        *reinterpret_cast<unsigned*>(&g_hd[(size_t)(r0 + 8) * DD + gch]) =
            pk(gn0 * siluf(ad_[nt][2]), gn1 * siluf(ad_[nt][3]));
    }
    __syncthreads();

    // fused local chunk scan: this token tile IS scan chunk (b, c)
    if (tid < 64) {
        int gch = blk * 64 + tid;
        float a = decay1(lAs, ldts, gch);
        float y = 0.0f;
#pragma unroll
        for (int s = 0; s < LC; s++)
            y = fmaf(a, y, sD[s * 66 + tid]);
        int b = tok0 >> 12;
        int c = (tok0 >> 6) & (NC - 1);
        g_csum[((size_t)(b * NC + c)) * DD + gch] = y;
    }
}

// ---------------- sB: inline carry + scan + h store (bf16) + rms partials ----------------
__global__ void __launch_bounds__(256) k_sB(const float* __restrict__ lAs,
                                            const float* __restrict__ ldts) {
    int c = blockIdx.x, b = blockIdx.y;
    int tid = threadIdx.x, lane = tid & 31, w = tid >> 5;
    int d0 = tid * 4;
    float4 a = decay4(lAs, ldts, d0);
    float4 aL;
    aL.x = __expf((float)LC * __logf(a.x));
    aL.y = __expf((float)LC * __logf(a.y));
    aL.z = __expf((float)LC * __logf(a.z));
    aL.w = __expf((float)LC * __logf(a.w));

    // carry prefix over earlier chunks (csum is 1 MB; L2-resident)
    float4 y = make_float4(0.f, 0.f, 0.f, 0.f);
    size_t csbase = (size_t)b * NC * DD + d0;
    for (int cp = 0; cp < c; cp++) {
        float4 cs = *reinterpret_cast<const float4*>(&g_csum[csbase + (size_t)cp * DD]);
        y.x = fmaf(y.x, aL.x, cs.x);
        y.y = fmaf(y.y, aL.y, cs.y);
        y.z = fmaf(y.z, aL.z, cs.z);
        y.w = fmaf(y.w, aL.w, cs.w);
    }

    int tokbase = b * TT_SEQ + c * LC;
    size_t base = (size_t)tokbase * DD + d0;
#pragma unroll 4
    for (int s = 0; s < LC; s++) {
        size_t row = base + (size_t)s * DD;
        uint2 du = *reinterpret_cast<const uint2*>(&g_drive[row]);
        uint2 hu = *reinterpret_cast<const uint2*>(&g_hd[row]);
        float2 dr0 = __bfloat1622float2(*reinterpret_cast<__nv_bfloat162*>(&du.x));
        float2 dr1 = __bfloat1622float2(*reinterpret_cast<__nv_bfloat162*>(&du.y));
        float2 hd0 = __bfloat1622float2(*reinterpret_cast<__nv_bfloat162*>(&hu.x));
        float2 hd1 = __bfloat1622float2(*reinterpret_cast<__nv_bfloat162*>(&hu.y));
        y.x = fmaf(a.x, y.x, dr0.x);
        y.y = fmaf(a.y, y.y, dr0.y);
        y.z = fmaf(a.z, y.z, dr1.x);
        y.w = fmaf(a.w, y.w, dr1.y);
        float hx = y.x + hd0.x, hy = y.y + hd0.y, hz = y.z + hd1.x, hw = y.w + hd1.y;
        uint2 ho;
        ho.x = pk(hx, hy);
        ho.y = pk(hz, hw);
        *reinterpret_cast<uint2*>(&g_hn[row]) = ho;
        float ss = hx * hx + hy * hy + hz * hz + hw * hw;
#pragma unroll
        for (int off = 16; off > 0; off >>= 1) ss += __shfl_xor_sync(0xffffffffu, ss, off);
        if (lane == 0) g_sspart[(size_t)(tokbase + s) * 8 + w] = ss;
    }
}

// ---------------- rstd for h ----------------
__global__ void __launch_bounds__(256) k_rstd() {
    int tok = blockIdx.x * 256 + threadIdx.x;
    const float4* p = reinterpret_cast<const float4*>(&g_sspart[(size_t)tok * 8]);
    float4 a = p[0], b = p[1];
    float s = a.x + a.y + a.z + a.w + b.x + b.y + b.z + b.w;
    g_rsh[tok] = rsqrtf(s * (1.0f / DD) + EPSV);
}

// ---------------- G2: r = silu(bd(concat[hn*rsh, x*rsx, shift(x*rsx)], w_post)) ----------------
__device__ __forceinline__ void stage_A_cat(unsigned* sA, const float* __restrict__ x,
                                            int tok0, int gcat0, int tid) {
#pragma unroll
    for (int it = 0; it < 4; ++it) {
        int idx = tid + it * 256;
        int i  = idx >> 4;
        int j0 = (idx & 15) << 2;
        int gcat = gcat0 + j0;
        int tok = tok0 + i;
        float4 v;
        float sc;
        if (gcat < 1024) {
            uint2 u = *reinterpret_cast<const uint2*>(&g_hn[(size_t)tok * DD + gcat]);
            float2 lo = __bfloat1622float2(*reinterpret_cast<__nv_bfloat162*>(&u.x));
            float2 hi = __bfloat1622float2(*reinterpret_cast<__nv_bfloat162*>(&u.y));
            v = make_float4(lo.x, lo.y, hi.x, hi.y);
            sc = g_rsh[tok];
        } else if (gcat < 2048) {
            v = *reinterpret_cast<const float4*>(&x[(size_t)tok * DD + (gcat - 1024)]);
            sc = g_rsx[tok];
        } else {
            if ((tok & (TT_SEQ - 1)) == 0) { v = make_float4(0.f, 0.f, 0.f, 0.f); sc = 0.0f; }
            else {
                v = *reinterpret_cast<const float4*>(&x[(size_t)(tok - 1) * DD + (gcat - 2048)]);
                sc = g_rsx[tok - 1];
            }
        }
        v.x *= sc; v.y *= sc; v.z *= sc; v.w *= sc;
        put_A4(sA, i, j0, v);
    }
}

__global__ void __launch_bounds__(256) k_g2(const float* __restrict__ x,
                                            const float* __restrict__ wpost) {
    __shared__ unsigned sA[ASZ];
    __shared__ unsigned sB[BSZ];
    int blk = blockIdx.y;
    int tok0 = blockIdx.x * 64;
    int tid = threadIdx.x, lane = tid & 31, w = tid >> 5, wm = w & 3, wn = w >> 2;
    float acc[4][4] = {};
#pragma unroll
    for (int kt = 0; kt < 3; ++kt) {
        stage_A_cat(sA, x, tok0, blk * BIP + kt * 64, tid);
        stage_B(sB, wpost + (size_t)blk * 64 * BIP + kt * 64, BIP, tid);
        __syncthreads();
        mma_chunk(acc, sA, sB, wm, wn, lane);
        __syncthreads();
    }
    int g = lane >> 2, t = lane & 3;
    int r0 = tok0 + wm * 16 + g;
#pragma unroll
    for (int nt = 0; nt < 4; nt++) {
        int n = blk * 64 + (wn * 4 + nt) * 8 + t * 2;
        *reinterpret_cast<unsigned*>(&g_r[(size_t)r0 * DD + n]) =
            pk(siluf(acc[nt][0]), siluf(acc[nt][1]));
        *reinterpret_cast<unsigned*>(&g_r[(size_t)(r0 + 8) * DD + n]) =
            pk(siluf(acc[nt][2]), siluf(acc[nt][3]));
    }
}

// ---------------- G3: t = r @ lr_B^T ----------------
__global__ void __launch_bounds__(256) k_g3(const float* __restrict__ lrB) {
    __shared__ unsigned sA[ASZ];
    __shared__ unsigned sB[BSZ];
    int tok0 = blockIdx.x * 64;
    int tid = threadIdx.x, lane = tid & 31, w = tid >> 5, wm = w & 3, wn = w >> 2;
    float acc[4][4] = {};
    for (int kt = 0; kt < 16; ++kt) {
        stageA16(sA, g_r + (size_t)tok0 * DD + kt * 64, DD, tid);
        stage_B(sB, lrB + kt * 64, DD, tid);
        __syncthreads();
        mma_chunk(acc, sA, sB, wm, wn, lane);
        __syncthreads();
    }
    int g = lane >> 2, t = lane & 3;
    int r0 = tok0 + wm * 16 + g;
#pragma unroll
    for (int nt = 0; nt < 4; nt++) {
        int n = (wn * 4 + nt) * 8 + t * 2;
        *reinterpret_cast<float2*>(&g_t[(size_t)r0 * RANKR + n]) =
            make_float2(acc[nt][0], acc[nt][1]);
        *reinterpret_cast<float2*>(&g_t[(size_t)(r0 + 8) * RANKR + n]) =
            make_float2(acc[nt][2], acc[nt][3]);
    }
}

// ---------------- G4: out = x + bd(r, w_local) + t @ lr_A^T ----------------
__global__ void __launch_bounds__(256) k_g4(const float* __restrict__ x,
                                            const float* __restrict__ wloc,
                                            const float* __restrict__ lrA,
                                            float* __restrict__ out) {
    __shared__ unsigned sA[ASZ];
    __shared__ unsigned sB[BSZ];
    int blk = blockIdx.y;
    int tok0 = blockIdx.x * 64;
    int tid = threadIdx.x, lane = tid & 31, w = tid >> 5, wm = w & 3, wn = w >> 2;
    float acc[4][4] = {};

    stageA16(sA, g_r + (size_t)tok0 * DD + blk * 64, DD, tid);
    stage_B(sB, wloc + (size_t)blk * 4096, 64, tid);
    __syncthreads();
    mma_chunk(acc, sA, sB, wm, wn, lane);
    __syncthreads();

    stageA32<false>(sA, g_t + (size_t)tok0 * RANKR, (const float*)0, 0, RANKR, tid);
    stage_B(sB, lrA + (size_t)blk * 4096, 64, tid);
    __syncthreads();
    mma_chunk(acc, sA, sB, wm, wn, lane);

    int g = lane >> 2, t = lane & 3;
    int r0 = tok0 + wm * 16 + g;
#pragma unroll
    for (int nt = 0; nt < 4; nt++) {
        int n = blk * 64 + (wn * 4 + nt) * 8 + t * 2;
        size_t i0 = (size_t)r0 * DD + n;
        size_t i1 = (size_t)(r0 + 8) * DD + n;
        float2 x0 = *reinterpret_cast<const float2*>(&x[i0]);
        float2 x1 = *reinterpret_cast<const float2*>(&x[i1]);
        *reinterpret_cast<float2*>(&out[i0]) = make_float2(x0.x + acc[nt][0], x0.y + acc[nt][1]);
        *reinterpret_cast<float2*>(&out[i1]) = make_float2(x1.x + acc[nt][2], x1.y + acc[nt][3]);
    }
}

// ---------------- launch ----------------
extern "C" void kernel_launch(void* const* d_in, const int* in_sizes, int n_in,
                              void* d_out, int out_size) {
    const float* x    = (const float*)d_in[0];
    const int*   actk = (const int*)  d_in[1];
    const float* wseq = (const float*)d_in[2];
    const float* wdep = (const float*)d_in[3];
    const float* wpost= (const float*)d_in[4];
    const float* wloc = (const float*)d_in[5];
    const float* lrA  = (const float*)d_in[6];
    const float* lrB  = (const float*)d_in[7];
    const float* lAs  = (const float*)d_in[8];
    const float* ldts = (const float*)d_in[9];
    const float* lAd  = (const float*)d_in[10];
    const float* ldtd = (const float*)d_in[11];
    float* out = (float*)d_out;

    dim3 gGemm(NTOK / 64, NBLK);     // (256, 16)
    dim3 gScan(NC, BB);              // (64, 4)

    k_stats<<<NTOK / 8, 256>>>(x);
    k_g1<<<gGemm, 256>>>(x, wseq, wdep, lAd, ldtd, lAs, ldts, actk);
    k_sB<<<gScan, 256>>>(lAs, ldts);
    k_rstd<<<NTOK / 256, 256>>>();
    k_g2<<<gGemm, 256>>>(x, wpost);
    k_g3<<<NTOK / 64, 256>>>(lrB);
    k_g4<<<gGemm, 256>>>(x, wloc, lrA, out);
}

// round 5
// speedup vs baseline: 4.4257x; 1.0386x over previous
#include <cuda_runtime.h>
#include <cuda_bf16.h>
#include <math.h>

// ---------------- problem constants ----------------
#define BB 4
#define TT_SEQ 4096
#define DD 1024
#define NTOK (BB*TT_SEQ)          // 16384
#define NBLK 16
#define BIP 192
#define RANKR 64
#define NMEM 128
#define LC 64                     // scan chunk length
#define NC (TT_SEQ/LC)            // 64 chunks
#define EPSV 1.1920929e-07f

// fragment-slot strides
#define ASLOT 132                 // uints per (mt,ks) A slot (padded)
#define BSLOT 66                  // uints per (nt,ks) B slot (padded)
#define BSZ (32*BSLOT)            // 2112 uints per 64x64 B tile
#define ASZ64  (16*ASLOT)         // 2112 uints (M=64)
#define ASZ128 (32*ASLOT)         // 4224 uints (M=128)
#define SDS 66                    // sD row stride (floats)

// ---------------- scratch (device globals; no allocation) ----------------
__device__ __nv_bfloat16 g_xn   [NTOK*DD];   // bf16(x * rsx)
__device__ __nv_bfloat16 g_drive[NTOK*DD];
__device__ __nv_bfloat16 g_hd   [NTOK*DD];
__device__ __nv_bfloat16 g_hn   [NTOK*DD];   // UNNORMALIZED h
__device__ __nv_bfloat16 g_r    [NTOK*DD];
__device__ __nv_bfloat16 g_t    [NTOK*RANKR];
__device__ float g_csum [BB*NC*DD];
__device__ float g_rsx  [NTOK];
__device__ float g_rsh  [NTOK];

// pre-fragmented bf16 weights
__device__ unsigned g_wf_seq [NBLK*BSZ];
__device__ unsigned g_wf_dep [NBLK*BSZ];
__device__ unsigned g_wf_loc [NBLK*BSZ];
__device__ unsigned g_wf_lrA [NBLK*BSZ];
__device__ unsigned g_wf_post[NBLK*3*BSZ];
__device__ unsigned g_wf_lrB [16*BSZ];

__device__ __forceinline__ float siluf(float x) {
    return x / (1.0f + __expf(-x));
}

__device__ __forceinline__ unsigned pk(float a, float b) {
    unsigned r;
    asm("cvt.rn.bf16x2.f32 %0, %1, %2;" : "=r"(r) : "f"(b), "f"(a));
    return r;
}

__device__ __forceinline__ float decay1(const float* __restrict__ lA,
                                        const float* __restrict__ ldt, int d) {
    return fmaxf(__expf(-__expf(lA[d]) * __expf(ldt[d])), 1e-6f);
}

__device__ __forceinline__ float4 decay4(const float* __restrict__ lA,
                                         const float* __restrict__ ldt, int d0) {
    float4 r;
    r.x = decay1(lA, ldt, d0 + 0);
    r.y = decay1(lA, ldt, d0 + 1);
    r.z = decay1(lA, ldt, d0 + 2);
    r.w = decay1(lA, ldt, d0 + 3);
    return r;
}

// ---------------- bf16 MMA machinery ----------------
__device__ __forceinline__ void mma_bf16(float c[4], const unsigned a[4], const unsigned b[2]) {
    asm volatile("mma.sync.aligned.m16n8k16.row.col.f32.bf16.bf16.f32 "
        "{%0,%1,%2,%3}, {%4,%5,%6,%7}, {%8,%9}, {%0,%1,%2,%3};"
        : "+f"(c[0]), "+f"(c[1]), "+f"(c[2]), "+f"(c[3])
        : "r"(a[0]), "r"(a[1]), "r"(a[2]), "r"(a[3]), "r"(b[0]), "r"(b[1]));
}

// passthrough place: 4 consecutive-k bf16 (as uint2) for A row i, col j0
__device__ __forceinline__ void putA16(unsigned* sA, int i, int j0, uint2 u) {
    int mt = i >> 4, rr = i & 15, half = rr >> 3, g = rr & 7;
    int ks = j0 >> 4, kk = j0 & 15, hi = kk >> 3, t0 = (kk & 7) >> 1;
    unsigned* p = &sA[(mt * 4 + ks) * ASLOT + (g * 4 + t0) * 4 + half + 2 * hi];
    p[0] = u.x;
    p[4] = u.y;
}

// stage M x 64 A tile from bf16 row-major source (M = 64 or 128)
template<int M>
__device__ __forceinline__ void stageA16(unsigned* sA, const __nv_bfloat16* __restrict__ base,
                                         int rs, int tid) {
#pragma unroll
    for (int it = 0; it < M / 16; ++it) {
        int idx = tid + it * 256;
        int i  = idx >> 4;
        int j0 = (idx & 15) << 2;
        uint2 u = *reinterpret_cast<const uint2*>(base + (size_t)i * rs + j0);
        putA16(sA, i, j0, u);
    }
}

// copy one pre-fragmented 64x64 B tile (BSZ=2112 uints = 528 uint4)
__device__ __forceinline__ void stage_Bc(unsigned* sB, const unsigned* __restrict__ src, int tid) {
    const uint4* s4 = reinterpret_cast<const uint4*>(src);
    uint4* d4 = reinterpret_cast<uint4*>(sB);
    d4[tid]       = s4[tid];
    d4[tid + 256] = s4[tid + 256];
    if (tid < 16) d4[tid + 512] = s4[tid + 512];
}

// M=128 mma: warp w owns m16 tile w, all 8 n8 subtiles
__device__ __forceinline__ void mma_chunk128(float acc[8][4], const unsigned* sA,
                                             const unsigned* sB, int w, int lane) {
#pragma unroll
    for (int ks = 0; ks < 4; ks++) {
        unsigned a[4];
        *reinterpret_cast<uint4*>(a) =
            *reinterpret_cast<const uint4*>(&sA[(w * 4 + ks) * ASLOT + lane * 4]);
#pragma unroll
        for (int nt = 0; nt < 8; nt++) {
            unsigned b[2];
            *reinterpret_cast<uint2*>(b) =
                *reinterpret_cast<const uint2*>(&sB[(nt * 4 + ks) * BSLOT + lane * 2]);
            mma_bf16(acc[nt], a, b);
        }
    }
}

// M=64 mma (g3): warp wm=w&3 m16 tile, wn=w>>2 n32 half
__device__ __forceinline__ void mma_chunk64(float acc[4][4], const unsigned* sA,
                                            const unsigned* sB, int wm, int wn, int lane) {
#pragma unroll
    for (int ks = 0; ks < 4; ks++) {
        unsigned a[4];
        *reinterpret_cast<uint4*>(a) =
            *reinterpret_cast<const uint4*>(&sA[(wm * 4 + ks) * ASLOT + lane * 4]);
#pragma unroll
        for (int nt = 0; nt < 4; nt++) {
            unsigned b[2];
            *reinterpret_cast<uint2*>(b) =
                *reinterpret_cast<const uint2*>(&sB[((wn * 4 + nt) * 4 + ks) * BSLOT + lane * 2]);
            mma_bf16(acc[nt], a, b);
        }
    }
}

// ---------------- weight pre-fragmentation ----------------
__global__ void __launch_bounds__(256) k_wconv(const float* __restrict__ wseq,
                                               const float* __restrict__ wdep,
                                               const float* __restrict__ wloc,
                                               const float* __restrict__ lrA,
                                               const float* __restrict__ wpost,
                                               const float* __restrict__ lrB) {
    int t = blockIdx.x;  // 0..127
    const float* src;
    unsigned* dst;
    int rs;
    if (t < 16)       { src = wseq + (size_t)t * 4096;        dst = g_wf_seq + t * BSZ;        rs = 64; }
    else if (t < 32)  { int b = t - 16; src = wdep + (size_t)b * 4096; dst = g_wf_dep + b * BSZ; rs = 64; }
    else if (t < 48)  { int b = t - 32; src = wloc + (size_t)b * 4096; dst = g_wf_loc + b * BSZ; rs = 64; }
    else if (t < 64)  { int b = t - 48; src = lrA + (size_t)b * 4096;  dst = g_wf_lrA + b * BSZ; rs = 64; }
    else if (t < 112) { int i = t - 64; int b = i / 3, kt = i % 3;
                        src = wpost + (size_t)b * 64 * BIP + kt * 64;
                        dst = g_wf_post + i * BSZ; rs = BIP; }
    else              { int kt = t - 112; src = lrB + kt * 64; dst = g_wf_lrB + kt * BSZ; rs = DD; }
    int tid = threadIdx.x;
#pragma unroll
    for (int it = 0; it < 4; ++it) {
        int idx = tid + it * 256;
        int n  = idx >> 4;
        int k0 = (idx & 15) << 2;
        float4 v = *reinterpret_cast<const float4*>(src + (size_t)n * rs + k0);
        int nt = n >> 3, g = n & 7;
        int ks = k0 >> 4, kk = k0 & 15, hi = kk >> 3, t0 = (kk & 7) >> 1;
        unsigned* p = &dst[(nt * 4 + ks) * BSLOT + (g * 4 + t0) * 2 + hi];
        p[0] = pk(v.x, v.y);
        p[2] = pk(v.z, v.w);
    }
}

// ---------------- stats: rsx + g_xn = bf16(x*rsx) ----------------
__global__ void __launch_bounds__(256) k_stats(const float* __restrict__ x) {
    int w = threadIdx.x >> 5, lane = threadIdx.x & 31;
    int tok = blockIdx.x * 8 + w;
    const float4* xr = reinterpret_cast<const float4*>(x + (size_t)tok * DD);
    float4 v[8];
    float ss = 0.0f;
#pragma unroll
    for (int i = 0; i < 8; i++) {
        v[i] = xr[lane + i * 32];
        ss += v[i].x * v[i].x + v[i].y * v[i].y + v[i].z * v[i].z + v[i].w * v[i].w;
    }
#pragma unroll
    for (int off = 16; off > 0; off >>= 1) ss += __shfl_xor_sync(0xffffffffu, ss, off);
    ss = __shfl_sync(0xffffffffu, ss, 0);
    float sc = rsqrtf(ss * (1.0f / DD) + EPSV);
    if (lane == 0) g_rsx[tok] = sc;
    uint2* xo = reinterpret_cast<uint2*>(g_xn + (size_t)tok * DD);
#pragma unroll
    for (int i = 0; i < 8; i++) {
        uint2 o;
        o.x = pk(v[i].x * sc, v[i].y * sc);
        o.y = pk(v[i].z * sc, v[i].w * sc);
        xo[lane + i * 32] = o;
    }
}

// ---------------- gain helper ----------------
__device__ __forceinline__ float gain_of(int gch, float Kf, const float* __restrict__ lAd,
                                         const float* __restrict__ ldtd) {
    if (gch < NMEM) return Kf;
    float a1 = __expf(-__expf(lAd[gch - NMEM]) * __expf(ldtd[gch - NMEM]));
    float om = 1.0f - a1;
    if (fabsf(om) < 1e-6f) return Kf;
    return (1.0f - __expf(Kf * __logf(a1))) / fmaxf(om, 1e-8f);
}

// ---------------- G1: drive/hd GEMMs (M=128) + fused 2-chunk scan ----------------
__global__ void __launch_bounds__(256) k_g1(const float* __restrict__ lAd,
                                            const float* __restrict__ ldtd,
                                            const float* __restrict__ lAs,
                                            const float* __restrict__ ldts,
                                            const int* __restrict__ kptr) {
    __shared__ __align__(16) unsigned smem[ASZ128 + 2 * BSZ];  // 8448 uints; sD aliases all
    unsigned* sA  = smem;
    unsigned* sB1 = smem + ASZ128;
    unsigned* sB2 = smem + ASZ128 + BSZ;
    int blk = blockIdx.y;
    int tok0 = blockIdx.x * 128;
    int tid = threadIdx.x, lane = tid & 31, w = tid >> 5;

    stageA16<128>(sA, g_xn + (size_t)tok0 * DD + blk * 64, DD, tid);
    stage_Bc(sB1, g_wf_seq + blk * BSZ, tid);
    stage_Bc(sB2, g_wf_dep + blk * BSZ, tid);
    __syncthreads();

    float as_[8][4] = {}, ad_[8][4] = {};
#pragma unroll
    for (int ks = 0; ks < 4; ks++) {
        unsigned a[4];
        *reinterpret_cast<uint4*>(a) =
            *reinterpret_cast<const uint4*>(&sA[(w * 4 + ks) * ASLOT + lane * 4]);
#pragma unroll
        for (int nt = 0; nt < 8; nt++) {
            int off = (nt * 4 + ks) * BSLOT + lane * 2;
            unsigned b[2];
            *reinterpret_cast<uint2*>(b) = *reinterpret_cast<const uint2*>(&sB1[off]);
            mma_bf16(as_[nt], a, b);
            *reinterpret_cast<uint2*>(b) = *reinterpret_cast<const uint2*>(&sB2[off]);
            mma_bf16(ad_[nt], a, b);
        }
    }
    __syncthreads();                  // A/B dead; reuse smem as fp32 drive tile

    float* sD = reinterpret_cast<float*>(smem);   // [128 rows][stride 66]
    float Kf = (float)(*kptr);
    int g = lane >> 2, t = lane & 3;
    int rl0 = w * 16 + g;
    int r0 = tok0 + rl0;
#pragma unroll
    for (int nt = 0; nt < 8; nt++) {
        int nl = nt * 8 + t * 2;
        int gch = blk * 64 + nl;
        float gn0 = gain_of(gch, Kf, lAd, ldtd);
        float gn1 = gain_of(gch + 1, Kf, lAd, ldtd);
        float d0 = siluf(as_[nt][0]), d1 = siluf(as_[nt][1]);
        float d2 = siluf(as_[nt][2]), d3 = siluf(as_[nt][3]);
        *reinterpret_cast<unsigned*>(&g_drive[(size_t)r0 * DD + gch])       = pk(d0, d1);
        *reinterpret_cast<unsigned*>(&g_drive[(size_t)(r0 + 8) * DD + gch]) = pk(d2, d3);
        *reinterpret_cast<float2*>(&sD[rl0 * SDS + nl])       = make_float2(d0, d1);
        *reinterpret_cast<float2*>(&sD[(rl0 + 8) * SDS + nl]) = make_float2(d2, d3);
        *reinterpret_cast<unsigned*>(&g_hd[(size_t)r0 * DD + gch]) =
            pk(gn0 * siluf(ad_[nt][0]), gn1 * siluf(ad_[nt][1]));
        *reinterpret_cast<unsigned*>(&g_hd[(size_t)(r0 + 8) * DD + gch]) =
            pk(gn0 * siluf(ad_[nt][2]), gn1 * siluf(ad_[nt][3]));
    }
    __syncthreads();

    // fused local scans: tile = chunks (b, c) and (b, c+1)
    if (tid < 128) {
        int ch = tid & 63;
        int half = tid >> 6;
        int gch = blk * 64 + ch;
        float a = decay1(lAs, ldts, gch);
        float y = 0.0f;
        int rbase = half * 64;
#pragma unroll
        for (int s = 0; s < LC; s++)
            y = fmaf(a, y, sD[(rbase + s) * SDS + ch]);
        int b = tok0 >> 12;
        int c = ((tok0 >> 6) & (NC - 1)) + half;
        g_csum[((size_t)(b * NC + c)) * DD + gch] = y;
    }
}

// ---------------- sB: inline carry + scan + h(bf16) + fused rstd ----------------
__global__ void __launch_bounds__(256) k_sB(const float* __restrict__ lAs,
                                            const float* __restrict__ ldts) {
    __shared__ float part[LC][8];
    int c = blockIdx.x, b = blockIdx.y;
    int tid = threadIdx.x, lane = tid & 31, w = tid >> 5;
    int d0 = tid * 4;
    float4 a = decay4(lAs, ldts, d0);
    float4 aL;
    aL.x = __expf((float)LC * __logf(a.x));
    aL.y = __expf((float)LC * __logf(a.y));
    aL.z = __expf((float)LC * __logf(a.z));
    aL.w = __expf((float)LC * __logf(a.w));

    float4 y = make_float4(0.f, 0.f, 0.f, 0.f);
    size_t csbase = (size_t)b * NC * DD + d0;
    for (int cp = 0; cp < c; cp++) {
        float4 cs = *reinterpret_cast<const float4*>(&g_csum[csbase + (size_t)cp * DD]);
        y.x = fmaf(y.x, aL.x, cs.x);
        y.y = fmaf(y.y, aL.y, cs.y);
        y.z = fmaf(y.z, aL.z, cs.z);
        y.w = fmaf(y.w, aL.w, cs.w);
    }

    int tokbase = b * TT_SEQ + c * LC;
    size_t base = (size_t)tokbase * DD + d0;
#pragma unroll 4
    for (int s = 0; s < LC; s++) {
        size_t row = base + (size_t)s * DD;
        uint2 du = *reinterpret_cast<const uint2*>(&g_drive[row]);
        uint2 hu = *reinterpret_cast<const uint2*>(&g_hd[row]);
        float2 dr0 = __bfloat1622float2(*reinterpret_cast<__nv_bfloat162*>(&du.x));
        float2 dr1 = __bfloat1622float2(*reinterpret_cast<__nv_bfloat162*>(&du.y));
        float2 hd0 = __bfloat1622float2(*reinterpret_cast<__nv_bfloat162*>(&hu.x));
        float2 hd1 = __bfloat1622float2(*reinterpret_cast<__nv_bfloat162*>(&hu.y));
        y.x = fmaf(a.x, y.x, dr0.x);
        y.y = fmaf(a.y, y.y, dr0.y);
        y.z = fmaf(a.z, y.z, dr1.x);
        y.w = fmaf(a.w, y.w, dr1.y);
        float hx = y.x + hd0.x, hy = y.y + hd0.y, hz = y.z + hd1.x, hw = y.w + hd1.y;
        uint2 ho;
        ho.x = pk(hx, hy);
        ho.y = pk(hz, hw);
        *reinterpret_cast<uint2*>(&g_hn[row]) = ho;
        float ss = hx * hx + hy * hy + hz * hz + hw * hw;
#pragma unroll
        for (int off = 16; off > 0; off >>= 1) ss += __shfl_xor_sync(0xffffffffu, ss, off);
        if (lane == 0) part[s][w] = ss;
    }
    __syncthreads();
    if (tid < LC) {
        float s = part[tid][0] + part[tid][1] + part[tid][2] + part[tid][3]
                + part[tid][4] + part[tid][5] + part[tid][6] + part[tid][7];
        g_rsh[tokbase + tid] = rsqrtf(s * (1.0f / DD) + EPSV);
    }
}

// ---------------- G2: r = silu(bd(concat[hn*rsh, xn, shift(xn)], w_post)), M=128 ----------------
__device__ __forceinline__ void stage_A_cat(unsigned* sA, int tok0, int gcat0, int tid) {
#pragma unroll
    for (int it = 0; it < 8; ++it) {
        int idx = tid + it * 256;
        int i  = idx >> 4;
        int j0 = (idx & 15) << 2;
        int gcat = gcat0 + j0;
        int tok = tok0 + i;
        uint2 u;
        if (gcat < 1024) {
            uint2 h = *reinterpret_cast<const uint2*>(&g_hn[(size_t)tok * DD + gcat]);
            float sc = g_rsh[tok];
            float2 lo = __bfloat1622float2(*reinterpret_cast<__nv_bfloat162*>(&h.x));
            float2 hi = __bfloat1622float2(*reinterpret_cast<__nv_bfloat162*>(&h.y));
            u.x = pk(lo.x * sc, lo.y * sc);
            u.y = pk(hi.x * sc, hi.y * sc);
        } else if (gcat < 2048) {
            u = *reinterpret_cast<const uint2*>(&g_xn[(size_t)tok * DD + (gcat - 1024)]);
        } else {
            if ((tok & (TT_SEQ - 1)) == 0) { u.x = 0u; u.y = 0u; }
            else u = *reinterpret_cast<const uint2*>(&g_xn[(size_t)(tok - 1) * DD + (gcat - 2048)]);
        }
        putA16(sA, i, j0, u);
    }
}

__global__ void __launch_bounds__(256) k_g2() {
    __shared__ __align__(16) unsigned sA[ASZ128];
    __shared__ __align__(16) unsigned sB[BSZ];
    int blk = blockIdx.y;
    int tok0 = blockIdx.x * 128;
    int tid = threadIdx.x, lane = tid & 31, w = tid >> 5;
    float acc[8][4] = {};
#pragma unroll
    for (int kt = 0; kt < 3; ++kt) {
        stage_A_cat(sA, tok0, blk * BIP + kt * 64, tid);
        stage_Bc(sB, g_wf_post + (blk * 3 + kt) * BSZ, tid);
        __syncthreads();
        mma_chunk128(acc, sA, sB, w, lane);
        __syncthreads();
    }
    int g = lane >> 2, t = lane & 3;
    int r0 = tok0 + w * 16 + g;
#pragma unroll
    for (int nt = 0; nt < 8; nt++) {
        int n = blk * 64 + nt * 8 + t * 2;
        *reinterpret_cast<unsigned*>(&g_r[(size_t)r0 * DD + n]) =
            pk(siluf(acc[nt][0]), siluf(acc[nt][1]));
        *reinterpret_cast<unsigned*>(&g_r[(size_t)(r0 + 8) * DD + n]) =
            pk(siluf(acc[nt][2]), siluf(acc[nt][3]));
    }
}

// ---------------- G3: t = r @ lr_B^T (M=64) ----------------
__global__ void __launch_bounds__(256) k_g3() {
    __shared__ __align__(16) unsigned sA[ASZ64];
    __shared__ __align__(16) unsigned sB[BSZ];
    int tok0 = blockIdx.x * 64;
    int tid = threadIdx.x, lane = tid & 31, w = tid >> 5, wm = w & 3, wn = w >> 2;
    float acc[4][4] = {};
    for (int kt = 0; kt < 16; ++kt) {
        stageA16<64>(sA, g_r + (size_t)tok0 * DD + kt * 64, DD, tid);
        stage_Bc(sB, g_wf_lrB + kt * BSZ, tid);
        __syncthreads();
        mma_chunk64(acc, sA, sB, wm, wn, lane);
        __syncthreads();
    }
    int g = lane >> 2, t = lane & 3;
    int r0 = tok0 + wm * 16 + g;
#pragma unroll
    for (int nt = 0; nt < 4; nt++) {
        int n = (wn * 4 + nt) * 8 + t * 2;
        *reinterpret_cast<unsigned*>(&g_t[(size_t)r0 * RANKR + n]) =
            pk(acc[nt][0], acc[nt][1]);
        *reinterpret_cast<unsigned*>(&g_t[(size_t)(r0 + 8) * RANKR + n]) =
            pk(acc[nt][2], acc[nt][3]);
    }
}

// ---------------- G4: out = x + bd(r, w_local) + t @ lr_A^T (M=128) ----------------
__global__ void __launch_bounds__(256) k_g4(const float* __restrict__ x,
                                            float* __restrict__ out) {
    __shared__ __align__(16) unsigned sA[ASZ128];
    __shared__ __align__(16) unsigned sB[BSZ];
    int blk = blockIdx.y;
    int tok0 = blockIdx.x * 128;
    int tid = threadIdx.x, lane = tid & 31, w = tid >> 5;
    float acc[8][4] = {};

    stageA16<128>(sA, g_r + (size_t)tok0 * DD + blk * 64, DD, tid);
    stage_Bc(sB, g_wf_loc + blk * BSZ, tid);
    __syncthreads();
    mma_chunk128(acc, sA, sB, w, lane);
    __syncthreads();

    stageA16<128>(sA, g_t + (size_t)tok0 * RANKR, RANKR, tid);
    stage_Bc(sB, g_wf_lrA + blk * BSZ, tid);
    __syncthreads();
    mma_chunk128(acc, sA, sB, w, lane);

    int g = lane >> 2, t = lane & 3;
    int r0 = tok0 + w * 16 + g;
#pragma unroll
    for (int nt = 0; nt < 8; nt++) {
        int n = blk * 64 + nt * 8 + t * 2;
        size_t i0 = (size_t)r0 * DD + n;
        size_t i1 = (size_t)(r0 + 8) * DD + n;
        float2 x0 = *reinterpret_cast<const float2*>(&x[i0]);
        float2 x1 = *reinterpret_cast<const float2*>(&x[i1]);
        *reinterpret_cast<float2*>(&out[i0]) = make_float2(x0.x + acc[nt][0], x0.y + acc[nt][1]);
        *reinterpret_cast<float2*>(&out[i1]) = make_float2(x1.x + acc[nt][2], x1.y + acc[nt][3]);
    }
}

// ---------------- launch ----------------
extern "C" void kernel_launch(void* const* d_in, const int* in_sizes, int n_in,
                              void* d_out, int out_size) {
    const float* x    = (const float*)d_in[0];
    const int*   actk = (const int*)  d_in[1];
    const float* wseq = (const float*)d_in[2];
    const float* wdep = (const float*)d_in[3];
    const float* wpost= (const float*)d_in[4];
    const float* wloc = (const float*)d_in[5];
    const float* lrA  = (const float*)d_in[6];
    const float* lrB  = (const float*)d_in[7];
    const float* lAs  = (const float*)d_in[8];
    const float* ldts = (const float*)d_in[9];
    const float* lAd  = (const float*)d_in[10];
    const float* ldtd = (const float*)d_in[11];
    float* out = (float*)d_out;

    dim3 gGemm(NTOK / 128, NBLK);    // (128, 16)
    dim3 gScan(NC, BB);              // (64, 4)

    k_wconv<<<128, 256>>>(wseq, wdep, wloc, lrA, wpost, lrB);
    k_stats<<<NTOK / 8, 256>>>(x);
    k_g1<<<gGemm, 256>>>(lAd, ldtd, lAs, ldts, actk);
    k_sB<<<gScan, 256>>>(lAs, ldts);
    k_g2<<<gGemm, 256>>>();
    k_g3<<<NTOK / 64, 256>>>();
    k_g4<<<gGemm, 256>>>(x, out);
}

// round 6
// speedup vs baseline: 4.9464x; 1.1177x over previous
#include <cuda_runtime.h>
#include <cuda_bf16.h>
#include <math.h>

// ---------------- problem constants ----------------
#define BB 4
#define TT_SEQ 4096
#define DD 1024
#define NTOK (BB*TT_SEQ)          // 16384
#define NBLK 16
#define BIP 192
#define RANKR 64
#define NMEM 128
#define LC 32                     // scan chunk length
#define NC (TT_SEQ/LC)            // 128 chunks
#define EPSV 1.1920929e-07f
#define NT128 (NTOK/128)          // 128

// fragment-slot strides
#define ASLOT 132                 // uints per (mt,ks) A slot (padded)
#define BSLOT 66                  // uints per (nt,ks) B slot (padded)
#define BSZ (32*BSLOT)            // 2112 uints per 64x64 B tile
#define ASZ64  (16*ASLOT)         // 2112 uints
#define ASZ128 (32*ASLOT)         // 4224 uints
#define SDS 66                    // sD row stride (floats)

// ---------------- scratch (device globals; no allocation) ----------------
__device__ __nv_bfloat16 g_xn   [NTOK*DD];
__device__ __nv_bfloat16 g_drive[NTOK*DD];
__device__ __nv_bfloat16 g_hd   [NTOK*DD];
__device__ __nv_bfloat16 g_hn   [NTOK*DD];
__device__ float g_csum [BB*NC*DD];
__device__ float g_rsx  [NTOK];
__device__ float g_rsh  [NTOK];

// fragment-major activations (r and t), 16B-aligned for cp.async
__device__ uint4 g_rf[NT128*16*(ASZ128/4)];
__device__ uint4 g_tf[NT128*(ASZ128/4)];

// pre-fragmented bf16 weights (uint4 for 16B alignment)
__device__ uint4 g_wf_seq [NBLK*BSZ/4];
__device__ uint4 g_wf_dep [NBLK*BSZ/4];
__device__ uint4 g_wf_loc [NBLK*BSZ/4];
__device__ uint4 g_wf_lrA [NBLK*BSZ/4];
__device__ uint4 g_wf_post[NBLK*3*BSZ/4];
__device__ uint4 g_wf_lrB [16*BSZ/4];

__device__ __forceinline__ float siluf(float x) {
    return x / (1.0f + __expf(-x));
}

__device__ __forceinline__ unsigned pk(float a, float b) {
    unsigned r;
    asm("cvt.rn.bf16x2.f32 %0, %1, %2;" : "=r"(r) : "f"(b), "f"(a));
    return r;
}

__device__ __forceinline__ float decay1(const float* __restrict__ lA,
                                        const float* __restrict__ ldt, int d) {
    return fmaxf(__expf(-__expf(lA[d]) * __expf(ldt[d])), 1e-6f);
}

__device__ __forceinline__ float4 decay4(const float* __restrict__ lA,
                                         const float* __restrict__ ldt, int d0) {
    float4 r;
    r.x = decay1(lA, ldt, d0 + 0);
    r.y = decay1(lA, ldt, d0 + 1);
    r.z = decay1(lA, ldt, d0 + 2);
    r.w = decay1(lA, ldt, d0 + 3);
    return r;
}

// ---------------- cp.async helpers ----------------
__device__ __forceinline__ unsigned sptr(const void* p) {
    return (unsigned)__cvta_generic_to_shared(p);
}
__device__ __forceinline__ void cpa16(unsigned d, const void* s) {
    asm volatile("cp.async.cg.shared.global [%0], [%1], 16;" :: "r"(d), "l"(s));
}
__device__ __forceinline__ void cp_commit() {
    asm volatile("cp.async.commit_group;");
}
template<int N>
__device__ __forceinline__ void cp_wait() {
    asm volatile("cp.async.wait_group %0;" :: "n"(N));
}
template<int N4>
__device__ __forceinline__ void cpcopy(unsigned dsm, const uint4* __restrict__ src, int tid) {
#pragma unroll
    for (int i = tid; i < N4; i += 256) cpa16(dsm + i * 16, src + i);
}

// ---------------- bf16 MMA machinery ----------------
__device__ __forceinline__ void mma_bf16(float c[4], const unsigned a[4], const unsigned b[2]) {
    asm volatile("mma.sync.aligned.m16n8k16.row.col.f32.bf16.bf16.f32 "
        "{%0,%1,%2,%3}, {%4,%5,%6,%7}, {%8,%9}, {%0,%1,%2,%3};"
        : "+f"(c[0]), "+f"(c[1]), "+f"(c[2]), "+f"(c[3])
        : "r"(a[0]), "r"(a[1]), "r"(a[2]), "r"(a[3]), "r"(b[0]), "r"(b[1]));
}

__device__ __forceinline__ void putA16(unsigned* sA, int i, int j0, uint2 u) {
    int mt = i >> 4, rr = i & 15, half = rr >> 3, g = rr & 7;
    int ks = j0 >> 4, kk = j0 & 15, hi = kk >> 3, t0 = (kk & 7) >> 1;
    unsigned* p = &sA[(mt * 4 + ks) * ASLOT + (g * 4 + t0) * 4 + half + 2 * hi];
    p[0] = u.x;
    p[4] = u.y;
}

template<int M>
__device__ __forceinline__ void stageA16(unsigned* sA, const __nv_bfloat16* __restrict__ base,
                                         int rs, int tid) {
#pragma unroll
    for (int it = 0; it < M / 16; ++it) {
        int idx = tid + it * 256;
        int i  = idx >> 4;
        int j0 = (idx & 15) << 2;
        uint2 u = *reinterpret_cast<const uint2*>(base + (size_t)i * rs + j0);
        putA16(sA, i, j0, u);
    }
}

__device__ __forceinline__ void mma_chunk128(float acc[8][4], const unsigned* sA,
                                             const unsigned* sB, int w, int lane) {
#pragma unroll
    for (int ks = 0; ks < 4; ks++) {
        unsigned a[4];
        *reinterpret_cast<uint4*>(a) =
            *reinterpret_cast<const uint4*>(&sA[(w * 4 + ks) * ASLOT + lane * 4]);
#pragma unroll
        for (int nt = 0; nt < 8; nt++) {
            unsigned b[2];
            *reinterpret_cast<uint2*>(b) =
                *reinterpret_cast<const uint2*>(&sB[(nt * 4 + ks) * BSLOT + lane * 2]);
            mma_bf16(acc[nt], a, b);
        }
    }
}

__device__ __forceinline__ void mma_chunk64(float acc[4][4], const unsigned* sA,
                                            const unsigned* sB, int wm, int wn, int lane) {
#pragma unroll
    for (int ks = 0; ks < 4; ks++) {
        unsigned a[4];
        *reinterpret_cast<uint4*>(a) =
            *reinterpret_cast<const uint4*>(&sA[(wm * 4 + ks) * ASLOT + lane * 4]);
#pragma unroll
        for (int nt = 0; nt < 4; nt++) {
            unsigned b[2];
            *reinterpret_cast<uint2*>(b) =
                *reinterpret_cast<const uint2*>(&sB[((wn * 4 + nt) * 4 + ks) * BSLOT + lane * 2]);
            mma_bf16(acc[nt], a, b);
        }
    }
}

// ---------------- weight pre-fragmentation ----------------
__global__ void __launch_bounds__(256) k_wconv(const float* __restrict__ wseq,
                                               const float* __restrict__ wdep,
                                               const float* __restrict__ wloc,
                                               const float* __restrict__ lrA,
                                               const float* __restrict__ wpost,
                                               const float* __restrict__ lrB) {
    int t = blockIdx.x;  // 0..127
    const float* src;
    unsigned* dst;
    int rs;
    if (t < 16)       { src = wseq + (size_t)t * 4096; dst = (unsigned*)g_wf_seq + t * BSZ; rs = 64; }
    else if (t < 32)  { int b = t - 16; src = wdep + (size_t)b * 4096; dst = (unsigned*)g_wf_dep + b * BSZ; rs = 64; }
    else if (t < 48)  { int b = t - 32; src = wloc + (size_t)b * 4096; dst = (unsigned*)g_wf_loc + b * BSZ; rs = 64; }
    else if (t < 64)  { int b = t - 48; src = lrA + (size_t)b * 4096;  dst = (unsigned*)g_wf_lrA + b * BSZ; rs = 64; }
    else if (t < 112) { int i = t - 64; int b = i / 3, kt = i % 3;
                        src = wpost + (size_t)b * 64 * BIP + kt * 64;
                        dst = (unsigned*)g_wf_post + i * BSZ; rs = BIP; }
    else              { int kt = t - 112; src = lrB + kt * 64; dst = (unsigned*)g_wf_lrB + kt * BSZ; rs = DD; }
    int tid = threadIdx.x;
#pragma unroll
    for (int it = 0; it < 4; ++it) {
        int idx = tid + it * 256;
        int n  = idx >> 4;
        int k0 = (idx & 15) << 2;
        float4 v = *reinterpret_cast<const float4*>(src + (size_t)n * rs + k0);
        int nt = n >> 3, g = n & 7;
        int ks = k0 >> 4, kk = k0 & 15, hi = kk >> 3, t0 = (kk & 7) >> 1;
        unsigned* p = &dst[(nt * 4 + ks) * BSLOT + (g * 4 + t0) * 2 + hi];
        p[0] = pk(v.x, v.y);
        p[2] = pk(v.z, v.w);
    }
}

// ---------------- stats: rsx + g_xn = bf16(x*rsx) ----------------
__global__ void __launch_bounds__(256) k_stats(const float* __restrict__ x) {
    int w = threadIdx.x >> 5, lane = threadIdx.x & 31;
    int tok = blockIdx.x * 8 + w;
    const float4* xr = reinterpret_cast<const float4*>(x + (size_t)tok * DD);
    float4 v[8];
    float ss = 0.0f;
#pragma unroll
    for (int i = 0; i < 8; i++) {
        v[i] = xr[lane + i * 32];
        ss += v[i].x * v[i].x + v[i].y * v[i].y + v[i].z * v[i].z + v[i].w * v[i].w;
    }
#pragma unroll
    for (int off = 16; off > 0; off >>= 1) ss += __shfl_xor_sync(0xffffffffu, ss, off);
    ss = __shfl_sync(0xffffffffu, ss, 0);
    float sc = rsqrtf(ss * (1.0f / DD) + EPSV);
    if (lane == 0) g_rsx[tok] = sc;
    uint2* xo = reinterpret_cast<uint2*>(g_xn + (size_t)tok * DD);
#pragma unroll
    for (int i = 0; i < 8; i++) {
        uint2 o;
        o.x = pk(v[i].x * sc, v[i].y * sc);
        o.y = pk(v[i].z * sc, v[i].w * sc);
        xo[lane + i * 32] = o;
    }
}

// ---------------- gain helper ----------------
__device__ __forceinline__ float gain_of(int gch, float Kf, const float* __restrict__ lAd,
                                         const float* __restrict__ ldtd) {
    if (gch < NMEM) return Kf;
    float a1 = __expf(-__expf(lAd[gch - NMEM]) * __expf(ldtd[gch - NMEM]));
    float om = 1.0f - a1;
    if (fabsf(om) < 1e-6f) return Kf;
    return (1.0f - __expf(Kf * __logf(a1))) / fmaxf(om, 1e-8f);
}

// ---------------- G1: drive/hd GEMMs (M=128) + fused 4x32 local scans ----------------
__global__ void __launch_bounds__(256) k_g1(const float* __restrict__ lAd,
                                            const float* __restrict__ ldtd,
                                            const float* __restrict__ lAs,
                                            const float* __restrict__ ldts,
                                            const int* __restrict__ kptr) {
    __shared__ __align__(16) unsigned smem[ASZ128 + 2 * BSZ];  // 8448 uints
    unsigned* sA  = smem;
    unsigned* sB1 = smem + ASZ128;
    unsigned* sB2 = smem + ASZ128 + BSZ;
    int blk = blockIdx.y;
    int tok0 = blockIdx.x * 128;
    int tid = threadIdx.x, lane = tid & 31, w = tid >> 5;

    cpcopy<528>(sptr(sB1), g_wf_seq + (size_t)blk * 528, tid);
    cpcopy<528>(sptr(sB2), g_wf_dep + (size_t)blk * 528, tid);
    cp_commit();
    stageA16<128>(sA, g_xn + (size_t)tok0 * DD + blk * 64, DD, tid);
    cp_wait<0>();
    __syncthreads();

    float as_[8][4] = {}, ad_[8][4] = {};
#pragma unroll
    for (int ks = 0; ks < 4; ks++) {
        unsigned a[4];
        *reinterpret_cast<uint4*>(a) =
            *reinterpret_cast<const uint4*>(&sA[(w * 4 + ks) * ASLOT + lane * 4]);
#pragma unroll
        for (int nt = 0; nt < 8; nt++) {
            int off = (nt * 4 + ks) * BSLOT + lane * 2;
            unsigned b[2];
            *reinterpret_cast<uint2*>(b) = *reinterpret_cast<const uint2*>(&sB1[off]);
            mma_bf16(as_[nt], a, b);
            *reinterpret_cast<uint2*>(b) = *reinterpret_cast<const uint2*>(&sB2[off]);
            mma_bf16(ad_[nt], a, b);
        }
    }
    __syncthreads();

    float* sD = reinterpret_cast<float*>(smem);   // [128 rows][stride 66]
    float Kf = (float)(*kptr);
    int g = lane >> 2, t = lane & 3;
    int rl0 = w * 16 + g;
    int r0 = tok0 + rl0;
#pragma unroll
    for (int nt = 0; nt < 8; nt++) {
        int nl = nt * 8 + t * 2;
        int gch = blk * 64 + nl;
        float gn0 = gain_of(gch, Kf, lAd, ldtd);
        float gn1 = gain_of(gch + 1, Kf, lAd, ldtd);
        float d0 = siluf(as_[nt][0]), d1 = siluf(as_[nt][1]);
        float d2 = siluf(as_[nt][2]), d3 = siluf(as_[nt][3]);
        *reinterpret_cast<unsigned*>(&g_drive[(size_t)r0 * DD + gch])       = pk(d0, d1);
        *reinterpret_cast<unsigned*>(&g_drive[(size_t)(r0 + 8) * DD + gch]) = pk(d2, d3);
        *reinterpret_cast<float2*>(&sD[rl0 * SDS + nl])       = make_float2(d0, d1);
        *reinterpret_cast<float2*>(&sD[(rl0 + 8) * SDS + nl]) = make_float2(d2, d3);
        *reinterpret_cast<unsigned*>(&g_hd[(size_t)r0 * DD + gch]) =
            pk(gn0 * siluf(ad_[nt][0]), gn1 * siluf(ad_[nt][1]));
        *reinterpret_cast<unsigned*>(&g_hd[(size_t)(r0 + 8) * DD + gch]) =
            pk(gn0 * siluf(ad_[nt][2]), gn1 * siluf(ad_[nt][3]));
    }
    __syncthreads();

    // fused local scans: tile = 4 chunks of 32 tokens
    {
        int ch = tid & 63;
        int quarter = tid >> 6;
        int gch = blk * 64 + ch;
        float a = decay1(lAs, ldts, gch);
        float y = 0.0f;
        int rbase = quarter * 32;
#pragma unroll
        for (int s = 0; s < LC; s++)
            y = fmaf(a, y, sD[(rbase + s) * SDS + ch]);
        int b = tok0 >> 12;
        int c = ((tok0 >> 5) & (NC - 1)) + quarter;
        g_csum[((size_t)(b * NC + c)) * DD + gch] = y;
    }
}

// ---------------- sB: inline carry + scan + h(bf16) + fused rstd ----------------
__global__ void __launch_bounds__(256) k_sB(const float* __restrict__ lAs,
                                            const float* __restrict__ ldts) {
    __shared__ float part[LC][8];
    int c = blockIdx.x, b = blockIdx.y;
    int tid = threadIdx.x, lane = tid & 31, w = tid >> 5;
    int d0 = tid * 4;
    float4 a = decay4(lAs, ldts, d0);
    float4 aL;
    aL.x = __expf((float)LC * __logf(a.x));
    aL.y = __expf((float)LC * __logf(a.y));
    aL.z = __expf((float)LC * __logf(a.z));
    aL.w = __expf((float)LC * __logf(a.w));

    float4 y = make_float4(0.f, 0.f, 0.f, 0.f);
    size_t csbase = (size_t)b * NC * DD + d0;
#pragma unroll 4
    for (int cp = 0; cp < c; cp++) {
        float4 cs = *reinterpret_cast<const float4*>(&g_csum[csbase + (size_t)cp * DD]);
        y.x = fmaf(y.x, aL.x, cs.x);
        y.y = fmaf(y.y, aL.y, cs.y);
        y.z = fmaf(y.z, aL.z, cs.z);
        y.w = fmaf(y.w, aL.w, cs.w);
    }

    int tokbase = b * TT_SEQ + c * LC;
    size_t base = (size_t)tokbase * DD + d0;
#pragma unroll 4
    for (int s = 0; s < LC; s++) {
        size_t row = base + (size_t)s * DD;
        uint2 du = *reinterpret_cast<const uint2*>(&g_drive[row]);
        uint2 hu = *reinterpret_cast<const uint2*>(&g_hd[row]);
        float2 dr0 = __bfloat1622float2(*reinterpret_cast<__nv_bfloat162*>(&du.x));
        float2 dr1 = __bfloat1622float2(*reinterpret_cast<__nv_bfloat162*>(&du.y));
        float2 hd0 = __bfloat1622float2(*reinterpret_cast<__nv_bfloat162*>(&hu.x));
        float2 hd1 = __bfloat1622float2(*reinterpret_cast<__nv_bfloat162*>(&hu.y));
        y.x = fmaf(a.x, y.x, dr0.x);
        y.y = fmaf(a.y, y.y, dr0.y);
        y.z = fmaf(a.z, y.z, dr1.x);
        y.w = fmaf(a.w, y.w, dr1.y);
        float hx = y.x + hd0.x, hy = y.y + hd0.y, hz = y.z + hd1.x, hw = y.w + hd1.y;
        uint2 ho;
        ho.x = pk(hx, hy);
        ho.y = pk(hz, hw);
        *reinterpret_cast<uint2*>(&g_hn[row]) = ho;
        float ss = hx * hx + hy * hy + hz * hz + hw * hw;
#pragma unroll
        for (int off = 16; off > 0; off >>= 1) ss += __shfl_xor_sync(0xffffffffu, ss, off);
        if (lane == 0) part[s][w] = ss;
    }
    __syncthreads();
    if (tid < LC) {
        float s = part[tid][0] + part[tid][1] + part[tid][2] + part[tid][3]
                + part[tid][4] + part[tid][5] + part[tid][6] + part[tid][7];
        g_rsh[tokbase + tid] = rsqrtf(s * (1.0f / DD) + EPSV);
    }
}

// ---------------- G2 helpers: concat A prefetch ----------------
struct CatRegs { uint2 u[8]; float sc[8]; };

__device__ __forceinline__ void catA_load(CatRegs& r, int tok0, int gcat0, int tid) {
#pragma unroll
    for (int it = 0; it < 8; ++it) {
        int idx = tid + it * 256;
        int i  = idx >> 4;
        int j0 = (idx & 15) << 2;
        int gcat = gcat0 + j0;
        int tok = tok0 + i;
        uint2 u;
        float sc = 1.0f;
        if (gcat < 1024) {
            u = *reinterpret_cast<const uint2*>(&g_hn[(size_t)tok * DD + gcat]);
            sc = g_rsh[tok];
        } else if (gcat < 2048) {
            u = *reinterpret_cast<const uint2*>(&g_xn[(size_t)tok * DD + (gcat - 1024)]);
        } else {
            if ((tok & (TT_SEQ - 1)) == 0) { u.x = 0u; u.y = 0u; }
            else u = *reinterpret_cast<const uint2*>(&g_xn[(size_t)(tok - 1) * DD + (gcat - 2048)]);
        }
        r.u[it] = u;
        r.sc[it] = sc;
    }
}

__device__ __forceinline__ void catA_sts(unsigned* sA, const CatRegs& r, int gcat0, int tid) {
#pragma unroll
    for (int it = 0; it < 8; ++it) {
        int idx = tid + it * 256;
        int i  = idx >> 4;
        int j0 = (idx & 15) << 2;
        int gcat = gcat0 + j0;
        uint2 u = r.u[it];
        if (gcat < 1024) {
            float sc = r.sc[it];
            float2 lo = __bfloat1622float2(*reinterpret_cast<const __nv_bfloat162*>(&u.x));
            float2 hi = __bfloat1622float2(*reinterpret_cast<const __nv_bfloat162*>(&u.y));
            u.x = pk(lo.x * sc, lo.y * sc);
            u.y = pk(hi.x * sc, hi.y * sc);
        }
        putA16(sA, i, j0, u);
    }
}

// ---------------- G2: r = silu(bd(concat, w_post)) -> g_rf fragment layout ----------------
__global__ void __launch_bounds__(256) k_g2() {
    __shared__ __align__(16) unsigned sA[ASZ128];
    __shared__ __align__(16) unsigned sB[2][BSZ];
    int blk = blockIdx.y;
    int tok0 = blockIdx.x * 128;
    int tid = threadIdx.x, lane = tid & 31, w = tid >> 5;
    const uint4* wp = g_wf_post + (size_t)(blk * 3) * 528;

    cpcopy<528>(sptr(sB[0]), wp, tid);       cp_commit();
    cpcopy<528>(sptr(sB[1]), wp + 528, tid); cp_commit();

    CatRegs r;
    catA_load(r, tok0, blk * BIP, tid);
    catA_sts(sA, r, blk * BIP, tid);
    cp_wait<1>();
    __syncthreads();

    float acc[8][4] = {};
    // kt = 0
    catA_load(r, tok0, blk * BIP + 64, tid);
    mma_chunk128(acc, sA, sB[0], w, lane);
    __syncthreads();
    cpcopy<528>(sptr(sB[0]), wp + 1056, tid); cp_commit();
    catA_sts(sA, r, blk * BIP + 64, tid);
    cp_wait<1>();
    __syncthreads();
    // kt = 1
    catA_load(r, tok0, blk * BIP + 128, tid);
    mma_chunk128(acc, sA, sB[1], w, lane);
    __syncthreads();
    catA_sts(sA, r, blk * BIP + 128, tid);
    cp_wait<0>();
    __syncthreads();
    // kt = 2
    mma_chunk128(acc, sA, sB[0], w, lane);

    // epilogue -> g_rf (fragment layout, slab (tok0/128, blk))
    int g = lane >> 2, t = lane & 3;
    unsigned* rf = (unsigned*)g_rf + ((size_t)((tok0 >> 7) * 16 + blk)) * ASZ128;
#pragma unroll
    for (int nt = 0; nt < 8; nt++) {
        int ks = nt >> 1, hi = nt & 1;
        unsigned* p = rf + (w * 4 + ks) * ASLOT + (g * 4 + t) * 4 + 2 * hi;
        p[0] = pk(siluf(acc[nt][0]), siluf(acc[nt][1]));
        p[1] = pk(siluf(acc[nt][2]), siluf(acc[nt][3]));
    }
}

// ---------------- G3: t = r @ lr_B^T (M=64, 2-stage cp.async pipeline) ----------------
__device__ __forceinline__ void g3_issue(unsigned dA, unsigned dB, int slab16, int halfoff,
                                         int kt, int tid) {
    cpcopy<528>(dA, g_rf + (size_t)(slab16 + kt) * 1056 + halfoff, tid);
    cpcopy<528>(dB, g_wf_lrB + (size_t)kt * 528, tid);
    cp_commit();
}

__global__ void __launch_bounds__(256) k_g3() {
    __shared__ __align__(16) unsigned smem[2 * ASZ64 + 2 * BSZ];   // 8448 uints
    unsigned* sAb[2] = { smem, smem + ASZ64 };
    unsigned* sBb[2] = { smem + 2 * ASZ64, smem + 2 * ASZ64 + BSZ };
    int tok0 = blockIdx.x * 64;
    int tid = threadIdx.x, lane = tid & 31, w = tid >> 5, wm = w & 3, wn = w >> 2;
    int slab16 = (tok0 >> 7) * 16;
    int halfoff = ((tok0 >> 6) & 1) * 528;

    g3_issue(sptr(sAb[0]), sptr(sBb[0]), slab16, halfoff, 0, tid);
    g3_issue(sptr(sAb[1]), sptr(sBb[1]), slab16, halfoff, 1, tid);

    float acc[4][4] = {};
#pragma unroll
    for (int kt = 0; kt < 16; kt++) {
        if (kt < 15) cp_wait<1>(); else cp_wait<0>();
        __syncthreads();
        mma_chunk64(acc, sAb[kt & 1], sBb[kt & 1], wm, wn, lane);
        __syncthreads();
        if (kt + 2 < 16)
            g3_issue(sptr(sAb[kt & 1]), sptr(sBb[kt & 1]), slab16, halfoff, kt + 2, tid);
    }

    // epilogue -> g_tf fragment layout
    int g = lane >> 2, t = lane & 3;
    int mtg = ((tok0 & 64) >> 4) + wm;
    unsigned* tf = (unsigned*)g_tf + (size_t)(tok0 >> 7) * ASZ128;
#pragma unroll
    for (int nt = 0; nt < 4; nt++) {
        int ng = wn * 4 + nt;
        int ks = ng >> 1, hi = ng & 1;
        unsigned* p = tf + (mtg * 4 + ks) * ASLOT + (g * 4 + t) * 4 + 2 * hi;
        p[0] = pk(acc[nt][0], acc[nt][1]);
        p[1] = pk(acc[nt][2], acc[nt][3]);
    }
}

// ---------------- G4: out = x + bd(r, w_local) + t @ lr_A^T (M=128) ----------------
#define G4SMEM (2 * (ASZ128 + BSZ) * 4)   // 50688 bytes

__global__ void __launch_bounds__(256) k_g4(const float* __restrict__ x,
                                            float* __restrict__ out) {
    extern __shared__ __align__(16) unsigned dsm[];
    unsigned* sA0 = dsm;
    unsigned* sB0 = dsm + ASZ128;
    unsigned* sA1 = dsm + ASZ128 + BSZ;
    unsigned* sB1 = dsm + 2 * ASZ128 + BSZ;
    int blk = blockIdx.y;
    int tok0 = blockIdx.x * 128;
    int tid = threadIdx.x, lane = tid & 31, w = tid >> 5;
    int slab16 = (tok0 >> 7) * 16;

    cpcopy<1056>(sptr(sA0), g_rf + (size_t)(slab16 + blk) * 1056, tid);
    cpcopy<528>(sptr(sB0), g_wf_loc + (size_t)blk * 528, tid);
    cp_commit();
    cpcopy<1056>(sptr(sA1), g_tf + (size_t)(tok0 >> 7) * 1056, tid);
    cpcopy<528>(sptr(sB1), g_wf_lrA + (size_t)blk * 528, tid);
    cp_commit();

    float acc[8][4] = {};
    cp_wait<1>();
    __syncthreads();
    mma_chunk128(acc, sA0, sB0, w, lane);
    cp_wait<0>();
    __syncthreads();
    mma_chunk128(acc, sA1, sB1, w, lane);

    int g = lane >> 2, t = lane & 3;
    int r0 = tok0 + w * 16 + g;
#pragma unroll
    for (int nt = 0; nt < 8; nt++) {
        int n = blk * 64 + nt * 8 + t * 2;
        size_t i0 = (size_t)r0 * DD + n;
        size_t i1 = (size_t)(r0 + 8) * DD + n;
        float2 x0 = *reinterpret_cast<const float2*>(&x[i0]);
        float2 x1 = *reinterpret_cast<const float2*>(&x[i1]);
        *reinterpret_cast<float2*>(&out[i0]) = make_float2(x0.x + acc[nt][0], x0.y + acc[nt][1]);
        *reinterpret_cast<float2*>(&out[i1]) = make_float2(x1.x + acc[nt][2], x1.y + acc[nt][3]);
    }
}

// ---------------- launch ----------------
extern "C" void kernel_launch(void* const* d_in, const int* in_sizes, int n_in,
                              void* d_out, int out_size) {
    const float* x    = (const float*)d_in[0];
    const int*   actk = (const int*)  d_in[1];
    const float* wseq = (const float*)d_in[2];
    const float* wdep = (const float*)d_in[3];
    const float* wpost= (const float*)d_in[4];
    const float* wloc = (const float*)d_in[5];
    const float* lrA  = (const float*)d_in[6];
    const float* lrB  = (const float*)d_in[7];
    const float* lAs  = (const float*)d_in[8];
    const float* ldts = (const float*)d_in[9];
    const float* lAd  = (const float*)d_in[10];
    const float* ldtd = (const float*)d_in[11];
    float* out = (float*)d_out;

    static bool attr_done = false;
    if (!attr_done) {
        cudaFuncSetAttribute(k_g4, cudaFuncAttributeMaxDynamicSharedMemorySize, G4SMEM);
        attr_done = true;
    }

    dim3 gGemm(NTOK / 128, NBLK);    // (128, 16)
    dim3 gScan(NC, BB);              // (128, 4)

    k_wconv<<<128, 256>>>(wseq, wdep, wloc, lrA, wpost, lrB);
    k_stats<<<NTOK / 8, 256>>>(x);
    k_g1<<<gGemm, 256>>>(lAd, ldtd, lAs, ldts, actk);
    k_sB<<<gScan, 256>>>(lAs, ldts);
    k_g2<<<gGemm, 256>>>();
    k_g3<<<NTOK / 64, 256>>>();
    k_g4<<<gGemm, 256, G4SMEM>>>(x, out);
}

// round 7
// speedup vs baseline: 5.1261x; 1.0363x over previous
#include <cuda_runtime.h>
#include <cuda_bf16.h>
#include <math.h>

// ---------------- problem constants ----------------
#define BB 4
#define TT_SEQ 4096
#define DD 1024
#define NTOK (BB*TT_SEQ)          // 16384
#define NBLK 16
#define BIP 192
#define RANKR 64
#define NMEM 128
#define LC 32                     // scan chunk length
#define NC (TT_SEQ/LC)            // 128 chunks
#define EPSV 1.1920929e-07f
#define NT128 (NTOK/128)          // 128

// fragment-slot strides
#define ASLOT 132                 // uints per (mt,ks) A slot (padded)
#define BSLOT 66                  // uints per (nt,ks) B slot (padded)
#define BSZ (32*BSLOT)            // 2112 uints per 64x64 B tile
#define ASZ64  (16*ASLOT)         // 2112 uints
#define ASZ128 (32*ASLOT)         // 4224 uints
#define SDS 66                    // sD row stride (floats)

// ---------------- scratch (device globals; no allocation) ----------------
__device__ __nv_bfloat16 g_xn   [NTOK*DD];
__device__ __nv_bfloat16 g_drive[NTOK*DD];
__device__ __nv_bfloat16 g_hd   [NTOK*DD];
__device__ __nv_bfloat16 g_hn   [NTOK*DD];
__device__ float g_csum [BB*NC*DD];
__device__ float g_rsx  [NTOK];
__device__ float g_rsh  [NTOK];

// fragment-major activations (r and t), 16B-aligned for cp.async
__device__ uint4 g_rf[NT128*16*(ASZ128/4)];
__device__ uint4 g_tf[NT128*(ASZ128/4)];

// pre-fragmented bf16 weights
__device__ uint4 g_wf_seq [NBLK*BSZ/4];
__device__ uint4 g_wf_dep [NBLK*BSZ/4];
__device__ uint4 g_wf_loc [NBLK*BSZ/4];
__device__ uint4 g_wf_lrA [NBLK*BSZ/4];
__device__ uint4 g_wf_post[NBLK*3*BSZ/4];
__device__ uint4 g_wf_lrB [16*BSZ/4];

__device__ __forceinline__ float siluf(float x) {
    return x / (1.0f + __expf(-x));
}

__device__ __forceinline__ unsigned pk(float a, float b) {
    unsigned r;
    asm("cvt.rn.bf16x2.f32 %0, %1, %2;" : "=r"(r) : "f"(b), "f"(a));
    return r;
}

__device__ __forceinline__ float decay1(const float* __restrict__ lA,
                                        const float* __restrict__ ldt, int d) {
    return fmaxf(__expf(-__expf(lA[d]) * __expf(ldt[d])), 1e-6f);
}

// ---------------- cp.async helpers ----------------
__device__ __forceinline__ unsigned sptr(const void* p) {
    return (unsigned)__cvta_generic_to_shared(p);
}
__device__ __forceinline__ void cpa16(unsigned d, const void* s) {
    asm volatile("cp.async.cg.shared.global [%0], [%1], 16;" :: "r"(d), "l"(s));
}
__device__ __forceinline__ void cp_commit() {
    asm volatile("cp.async.commit_group;");
}
template<int N>
__device__ __forceinline__ void cp_wait() {
    asm volatile("cp.async.wait_group %0;" :: "n"(N));
}
template<int N4>
__device__ __forceinline__ void cpcopy(unsigned dsm, const uint4* __restrict__ src, int tid) {
#pragma unroll
    for (int i = tid; i < N4; i += 256) cpa16(dsm + i * 16, src + i);
}

// ---------------- bf16 MMA machinery ----------------
__device__ __forceinline__ void mma_bf16(float c[4], const unsigned a[4], const unsigned b[2]) {
    asm volatile("mma.sync.aligned.m16n8k16.row.col.f32.bf16.bf16.f32 "
        "{%0,%1,%2,%3}, {%4,%5,%6,%7}, {%8,%9}, {%0,%1,%2,%3};"
        : "+f"(c[0]), "+f"(c[1]), "+f"(c[2]), "+f"(c[3])
        : "r"(a[0]), "r"(a[1]), "r"(a[2]), "r"(a[3]), "r"(b[0]), "r"(b[1]));
}

__device__ __forceinline__ void putA16(unsigned* sA, int i, int j0, uint2 u) {
    int mt = i >> 4, rr = i & 15, half = rr >> 3, g = rr & 7;
    int ks = j0 >> 4, kk = j0 & 15, hi = kk >> 3, t0 = (kk & 7) >> 1;
    unsigned* p = &sA[(mt * 4 + ks) * ASLOT + (g * 4 + t0) * 4 + half + 2 * hi];
    p[0] = u.x;
    p[4] = u.y;
}

template<int M>
__device__ __forceinline__ void stageA16(unsigned* sA, const __nv_bfloat16* __restrict__ base,
                                         int rs, int tid) {
#pragma unroll
    for (int it = 0; it < M / 16; ++it) {
        int idx = tid + it * 256;
        int i  = idx >> 4;
        int j0 = (idx & 15) << 2;
        uint2 u = *reinterpret_cast<const uint2*>(base + (size_t)i * rs + j0);
        putA16(sA, i, j0, u);
    }
}

__device__ __forceinline__ void mma_chunk128(float acc[8][4], const unsigned* sA,
                                             const unsigned* sB, int w, int lane) {
#pragma unroll
    for (int ks = 0; ks < 4; ks++) {
        unsigned a[4];
        *reinterpret_cast<uint4*>(a) =
            *reinterpret_cast<const uint4*>(&sA[(w * 4 + ks) * ASLOT + lane * 4]);
#pragma unroll
        for (int nt = 0; nt < 8; nt++) {
            unsigned b[2];
            *reinterpret_cast<uint2*>(b) =
                *reinterpret_cast<const uint2*>(&sB[(nt * 4 + ks) * BSLOT + lane * 2]);
            mma_bf16(acc[nt], a, b);
        }
    }
}

__device__ __forceinline__ void mma_chunk64(float acc[4][4], const unsigned* sA,
                                            const unsigned* sB, int wm, int wn, int lane) {
#pragma unroll
    for (int ks = 0; ks < 4; ks++) {
        unsigned a[4];
        *reinterpret_cast<uint4*>(a) =
            *reinterpret_cast<const uint4*>(&sA[(wm * 4 + ks) * ASLOT + lane * 4]);
#pragma unroll
        for (int nt = 0; nt < 4; nt++) {
            unsigned b[2];
            *reinterpret_cast<uint2*>(b) =
                *reinterpret_cast<const uint2*>(&sB[((wn * 4 + nt) * 4 + ks) * BSLOT + lane * 2]);
            mma_bf16(acc[nt], a, b);
        }
    }
}

// ---------------- prep: weight fragmentation + x stats (one launch) ----------------
__global__ void __launch_bounds__(256) k_prep(const float* __restrict__ x,
                                              const float* __restrict__ wseq,
                                              const float* __restrict__ wdep,
                                              const float* __restrict__ wloc,
                                              const float* __restrict__ lrA,
                                              const float* __restrict__ wpost,
                                              const float* __restrict__ lrB) {
    int tid = threadIdx.x;
    if (blockIdx.x < 128) {
        int t = blockIdx.x;
        const float* src;
        unsigned* dst;
        int rs;
        if (t < 16)       { src = wseq + (size_t)t * 4096; dst = (unsigned*)g_wf_seq + t * BSZ; rs = 64; }
        else if (t < 32)  { int b = t - 16; src = wdep + (size_t)b * 4096; dst = (unsigned*)g_wf_dep + b * BSZ; rs = 64; }
        else if (t < 48)  { int b = t - 32; src = wloc + (size_t)b * 4096; dst = (unsigned*)g_wf_loc + b * BSZ; rs = 64; }
        else if (t < 64)  { int b = t - 48; src = lrA + (size_t)b * 4096;  dst = (unsigned*)g_wf_lrA + b * BSZ; rs = 64; }
        else if (t < 112) { int i = t - 64; int b = i / 3, kt = i % 3;
                            src = wpost + (size_t)b * 64 * BIP + kt * 64;
                            dst = (unsigned*)g_wf_post + i * BSZ; rs = BIP; }
        else              { int kt = t - 112; src = lrB + kt * 64; dst = (unsigned*)g_wf_lrB + kt * BSZ; rs = DD; }
#pragma unroll
        for (int it = 0; it < 4; ++it) {
            int idx = tid + it * 256;
            int n  = idx >> 4;
            int k0 = (idx & 15) << 2;
            float4 v = *reinterpret_cast<const float4*>(src + (size_t)n * rs + k0);
            int nt = n >> 3, g = n & 7;
            int ks = k0 >> 4, kk = k0 & 15, hi = kk >> 3, t0 = (kk & 7) >> 1;
            unsigned* p = &dst[(nt * 4 + ks) * BSLOT + (g * 4 + t0) * 2 + hi];
            p[0] = pk(v.x, v.y);
            p[2] = pk(v.z, v.w);
        }
    } else {
        int w = tid >> 5, lane = tid & 31;
        int tok = (blockIdx.x - 128) * 8 + w;
        const float4* xr = reinterpret_cast<const float4*>(x + (size_t)tok * DD);
        float4 v[8];
        float ss = 0.0f;
#pragma unroll
        for (int i = 0; i < 8; i++) {
            v[i] = xr[lane + i * 32];
            ss += v[i].x * v[i].x + v[i].y * v[i].y + v[i].z * v[i].z + v[i].w * v[i].w;
        }
#pragma unroll
        for (int off = 16; off > 0; off >>= 1) ss += __shfl_xor_sync(0xffffffffu, ss, off);
        ss = __shfl_sync(0xffffffffu, ss, 0);
        float sc = rsqrtf(ss * (1.0f / DD) + EPSV);
        if (lane == 0) g_rsx[tok] = sc;
        uint2* xo = reinterpret_cast<uint2*>(g_xn + (size_t)tok * DD);
#pragma unroll
        for (int i = 0; i < 8; i++) {
            uint2 o;
            o.x = pk(v[i].x * sc, v[i].y * sc);
            o.y = pk(v[i].z * sc, v[i].w * sc);
            xo[lane + i * 32] = o;
        }
    }
}

// ---------------- gain helper ----------------
__device__ __forceinline__ float gain_of(int gch, float Kf, const float* __restrict__ lAd,
                                         const float* __restrict__ ldtd) {
    if (gch < NMEM) return Kf;
    float a1 = __expf(-__expf(lAd[gch - NMEM]) * __expf(ldtd[gch - NMEM]));
    float om = 1.0f - a1;
    if (fabsf(om) < 1e-6f) return Kf;
    return (1.0f - __expf(Kf * __logf(a1))) / fmaxf(om, 1e-8f);
}

// ---------------- G1: drive/hd GEMMs (M=128) + fused 4x32 local scans ----------------
__global__ void __launch_bounds__(256) k_g1(const float* __restrict__ lAd,
                                            const float* __restrict__ ldtd,
                                            const float* __restrict__ lAs,
                                            const float* __restrict__ ldts,
                                            const int* __restrict__ kptr) {
    __shared__ __align__(16) unsigned smem[ASZ128 + 2 * BSZ];
    unsigned* sA  = smem;
    unsigned* sB1 = smem + ASZ128;
    unsigned* sB2 = smem + ASZ128 + BSZ;
    int blk = blockIdx.y;
    int tok0 = blockIdx.x * 128;
    int tid = threadIdx.x, lane = tid & 31, w = tid >> 5;

    cpcopy<528>(sptr(sB1), g_wf_seq + (size_t)blk * 528, tid);
    cpcopy<528>(sptr(sB2), g_wf_dep + (size_t)blk * 528, tid);
    cp_commit();
    stageA16<128>(sA, g_xn + (size_t)tok0 * DD + blk * 64, DD, tid);
    cp_wait<0>();
    __syncthreads();

    float as_[8][4] = {}, ad_[8][4] = {};
#pragma unroll
    for (int ks = 0; ks < 4; ks++) {
        unsigned a[4];
        *reinterpret_cast<uint4*>(a) =
            *reinterpret_cast<const uint4*>(&sA[(w * 4 + ks) * ASLOT + lane * 4]);
#pragma unroll
        for (int nt = 0; nt < 8; nt++) {
            int off = (nt * 4 + ks) * BSLOT + lane * 2;
            unsigned b[2];
            *reinterpret_cast<uint2*>(b) = *reinterpret_cast<const uint2*>(&sB1[off]);
            mma_bf16(as_[nt], a, b);
            *reinterpret_cast<uint2*>(b) = *reinterpret_cast<const uint2*>(&sB2[off]);
            mma_bf16(ad_[nt], a, b);
        }
    }
    __syncthreads();

    float* sD = reinterpret_cast<float*>(smem);   // [128 rows][stride 66]
    float Kf = (float)(*kptr);
    int g = lane >> 2, t = lane & 3;
    int rl0 = w * 16 + g;
    int r0 = tok0 + rl0;
#pragma unroll
    for (int nt = 0; nt < 8; nt++) {
        int nl = nt * 8 + t * 2;
        int gch = blk * 64 + nl;
        float gn0 = gain_of(gch, Kf, lAd, ldtd);
        float gn1 = gain_of(gch + 1, Kf, lAd, ldtd);
        float d0 = siluf(as_[nt][0]), d1 = siluf(as_[nt][1]);
        float d2 = siluf(as_[nt][2]), d3 = siluf(as_[nt][3]);
        *reinterpret_cast<unsigned*>(&g_drive[(size_t)r0 * DD + gch])       = pk(d0, d1);
        *reinterpret_cast<unsigned*>(&g_drive[(size_t)(r0 + 8) * DD + gch]) = pk(d2, d3);
        *reinterpret_cast<float2*>(&sD[rl0 * SDS + nl])       = make_float2(d0, d1);
        *reinterpret_cast<float2*>(&sD[(rl0 + 8) * SDS + nl]) = make_float2(d2, d3);
        *reinterpret_cast<unsigned*>(&g_hd[(size_t)r0 * DD + gch]) =
            pk(gn0 * siluf(ad_[nt][0]), gn1 * siluf(ad_[nt][1]));
        *reinterpret_cast<unsigned*>(&g_hd[(size_t)(r0 + 8) * DD + gch]) =
            pk(gn0 * siluf(ad_[nt][2]), gn1 * siluf(ad_[nt][3]));
    }
    __syncthreads();

    // fused local scans: tile = 4 chunks of 32 tokens
    {
        int ch = tid & 63;
        int quarter = tid >> 6;
        int gch = blk * 64 + ch;
        float a = decay1(lAs, ldts, gch);
        float y = 0.0f;
        int rbase = quarter * 32;
#pragma unroll
        for (int s = 0; s < LC; s++)
            y = fmaf(a, y, sD[(rbase + s) * SDS + ch]);
        int b = tok0 >> 12;
        int c = ((tok0 >> 5) & (NC - 1)) + quarter;
        g_csum[((size_t)(b * NC + c)) * DD + gch] = y;
    }
}

// ---------------- sB: pure streaming scan, channel-split, no reductions ----------------
__global__ void __launch_bounds__(256) k_sB(const float* __restrict__ lAs,
                                            const float* __restrict__ ldts) {
    int c = blockIdx.x, b = blockIdx.y;
    int d0 = blockIdx.z * 512 + threadIdx.x * 2;
    float ax = decay1(lAs, ldts, d0);
    float ay = decay1(lAs, ldts, d0 + 1);
    float aLx = __expf((float)LC * __logf(ax));
    float aLy = __expf((float)LC * __logf(ay));

    float yx = 0.0f, yy = 0.0f;
    size_t csbase = (size_t)b * NC * DD + d0;
#pragma unroll 4
    for (int cp = 0; cp < c; cp++) {
        float2 cs = *reinterpret_cast<const float2*>(&g_csum[csbase + (size_t)cp * DD]);
        yx = fmaf(yx, aLx, cs.x);
        yy = fmaf(yy, aLy, cs.y);
    }

    size_t base = (size_t)(b * TT_SEQ + c * LC) * DD + d0;
#pragma unroll 8
    for (int s = 0; s < LC; s++) {
        size_t row = base + (size_t)s * DD;
        unsigned du = *reinterpret_cast<const unsigned*>(&g_drive[row]);
        unsigned hu = *reinterpret_cast<const unsigned*>(&g_hd[row]);
        float2 dr = __bfloat1622float2(*reinterpret_cast<__nv_bfloat162*>(&du));
        float2 hd = __bfloat1622float2(*reinterpret_cast<__nv_bfloat162*>(&hu));
        yx = fmaf(ax, yx, dr.x);
        yy = fmaf(ay, yy, dr.y);
        *reinterpret_cast<unsigned*>(&g_hn[row]) = pk(yx + hd.x, yy + hd.y);
    }
}

// ---------------- rstd: warp-per-token over g_hn -> g_rsh ----------------
__global__ void __launch_bounds__(256) k_rstd() {
    int w = threadIdx.x >> 5, lane = threadIdx.x & 31;
    int tok = blockIdx.x * 8 + w;
    const uint4* hr = reinterpret_cast<const uint4*>(g_hn + (size_t)tok * DD);
    float ss = 0.0f;
#pragma unroll
    for (int i = 0; i < 4; i++) {
        uint4 u = hr[lane + i * 32];
        float2 a0 = __bfloat1622float2(*reinterpret_cast<__nv_bfloat162*>(&u.x));
        float2 a1 = __bfloat1622float2(*reinterpret_cast<__nv_bfloat162*>(&u.y));
        float2 a2 = __bfloat1622float2(*reinterpret_cast<__nv_bfloat162*>(&u.z));
        float2 a3 = __bfloat1622float2(*reinterpret_cast<__nv_bfloat162*>(&u.w));
        ss += a0.x * a0.x + a0.y * a0.y + a1.x * a1.x + a1.y * a1.y
            + a2.x * a2.x + a2.y * a2.y + a3.x * a3.x + a3.y * a3.y;
    }
#pragma unroll
    for (int off = 16; off > 0; off >>= 1) ss += __shfl_xor_sync(0xffffffffu, ss, off);
    if (lane == 0) g_rsh[tok] = rsqrtf(ss * (1.0f / DD) + EPSV);
}

// ---------------- G2 helpers: concat A prefetch ----------------
struct CatRegs { uint2 u[8]; float sc[8]; };

__device__ __forceinline__ void catA_load(CatRegs& r, int tok0, int gcat0, int tid) {
#pragma unroll
    for (int it = 0; it < 8; ++it) {
        int idx = tid + it * 256;
        int i  = idx >> 4;
        int j0 = (idx & 15) << 2;
        int gcat = gcat0 + j0;
        int tok = tok0 + i;
        uint2 u;
        float sc = 1.0f;
        if (gcat < 1024) {
            u = *reinterpret_cast<const uint2*>(&g_hn[(size_t)tok * DD + gcat]);
            sc = g_rsh[tok];
        } else if (gcat < 2048) {
            u = *reinterpret_cast<const uint2*>(&g_xn[(size_t)tok * DD + (gcat - 1024)]);
        } else {
            if ((tok & (TT_SEQ - 1)) == 0) { u.x = 0u; u.y = 0u; }
            else u = *reinterpret_cast<const uint2*>(&g_xn[(size_t)(tok - 1) * DD + (gcat - 2048)]);
        }
        r.u[it] = u;
        r.sc[it] = sc;
    }
}

__device__ __forceinline__ void catA_sts(unsigned* sA, const CatRegs& r, int gcat0, int tid) {
#pragma unroll
    for (int it = 0; it < 8; ++it) {
        int idx = tid + it * 256;
        int i  = idx >> 4;
        int j0 = (idx & 15) << 2;
        int gcat = gcat0 + j0;
        uint2 u = r.u[it];
        if (gcat < 1024) {
            float sc = r.sc[it];
            float2 lo = __bfloat1622float2(*reinterpret_cast<const __nv_bfloat162*>(&u.x));
            float2 hi = __bfloat1622float2(*reinterpret_cast<const __nv_bfloat162*>(&u.y));
            u.x = pk(lo.x * sc, lo.y * sc);
            u.y = pk(hi.x * sc, hi.y * sc);
        }
        putA16(sA, i, j0, u);
    }
}

// ---------------- G2: r = silu(bd(concat, w_post)) -> g_rf fragment layout ----------------
__global__ void __launch_bounds__(256) k_g2() {
    __shared__ __align__(16) unsigned sA[ASZ128];
    __shared__ __align__(16) unsigned sB[2][BSZ];
    int blk = blockIdx.y;
    int tok0 = blockIdx.x * 128;
    int tid = threadIdx.x, lane = tid & 31, w = tid >> 5;
    const uint4* wp = g_wf_post + (size_t)(blk * 3) * 528;

    cpcopy<528>(sptr(sB[0]), wp, tid);       cp_commit();
    cpcopy<528>(sptr(sB[1]), wp + 528, tid); cp_commit();

    CatRegs r;
    catA_load(r, tok0, blk * BIP, tid);
    catA_sts(sA, r, blk * BIP, tid);
    cp_wait<1>();
    __syncthreads();

    float acc[8][4] = {};
    // kt = 0
    catA_load(r, tok0, blk * BIP + 64, tid);
    mma_chunk128(acc, sA, sB[0], w, lane);
    __syncthreads();
    cpcopy<528>(sptr(sB[0]), wp + 1056, tid); cp_commit();
    catA_sts(sA, r, blk * BIP + 64, tid);
    cp_wait<1>();
    __syncthreads();
    // kt = 1
    catA_load(r, tok0, blk * BIP + 128, tid);
    mma_chunk128(acc, sA, sB[1], w, lane);
    __syncthreads();
    catA_sts(sA, r, blk * BIP + 128, tid);
    cp_wait<0>();
    __syncthreads();
    // kt = 2
    mma_chunk128(acc, sA, sB[0], w, lane);

    int g = lane >> 2, t = lane & 3;
    unsigned* rf = (unsigned*)g_rf + ((size_t)((tok0 >> 7) * 16 + blk)) * ASZ128;
#pragma unroll
    for (int nt = 0; nt < 8; nt++) {
        int ks = nt >> 1, hi = nt & 1;
        unsigned* p = rf + (w * 4 + ks) * ASLOT + (g * 4 + t) * 4 + 2 * hi;
        p[0] = pk(siluf(acc[nt][0]), siluf(acc[nt][1]));
        p[1] = pk(siluf(acc[nt][2]), siluf(acc[nt][3]));
    }
}

// ---------------- G3: t = r @ lr_B^T (M=64, 2-stage cp.async pipeline) ----------------
__device__ __forceinline__ void g3_issue(unsigned dA, unsigned dB, int slab16, int halfoff,
                                         int kt, int tid) {
    cpcopy<528>(dA, g_rf + (size_t)(slab16 + kt) * 1056 + halfoff, tid);
    cpcopy<528>(dB, g_wf_lrB + (size_t)kt * 528, tid);
    cp_commit();
}

__global__ void __launch_bounds__(256) k_g3() {
    __shared__ __align__(16) unsigned smem[2 * ASZ64 + 2 * BSZ];
    unsigned* sAb[2] = { smem, smem + ASZ64 };
    unsigned* sBb[2] = { smem + 2 * ASZ64, smem + 2 * ASZ64 + BSZ };
    int tok0 = blockIdx.x * 64;
    int tid = threadIdx.x, lane = tid & 31, w = tid >> 5, wm = w & 3, wn = w >> 2;
    int slab16 = (tok0 >> 7) * 16;
    int halfoff = ((tok0 >> 6) & 1) * 528;

    g3_issue(sptr(sAb[0]), sptr(sBb[0]), slab16, halfoff, 0, tid);
    g3_issue(sptr(sAb[1]), sptr(sBb[1]), slab16, halfoff, 1, tid);

    float acc[4][4] = {};
#pragma unroll
    for (int kt = 0; kt < 16; kt++) {
        if (kt < 15) cp_wait<1>(); else cp_wait<0>();
        __syncthreads();
        mma_chunk64(acc, sAb[kt & 1], sBb[kt & 1], wm, wn, lane);
        __syncthreads();
        if (kt + 2 < 16)
            g3_issue(sptr(sAb[kt & 1]), sptr(sBb[kt & 1]), slab16, halfoff, kt + 2, tid);
    }

    int g = lane >> 2, t = lane & 3;
    int mtg = ((tok0 & 64) >> 4) + wm;
    unsigned* tf = (unsigned*)g_tf + (size_t)(tok0 >> 7) * ASZ128;
#pragma unroll
    for (int nt = 0; nt < 4; nt++) {
        int ng = wn * 4 + nt;
        int ks = ng >> 1, hi = ng & 1;
        unsigned* p = tf + (mtg * 4 + ks) * ASLOT + (g * 4 + t) * 4 + 2 * hi;
        p[0] = pk(acc[nt][0], acc[nt][1]);
        p[1] = pk(acc[nt][2], acc[nt][3]);
    }
}

// ---------------- G4: out = x + bd(r, w_local) + t @ lr_A^T (M=128) ----------------
#define G4SMEM (2 * (ASZ128 + BSZ) * 4)   // 50688 bytes

__global__ void __launch_bounds__(256) k_g4(const float* __restrict__ x,
                                            float* __restrict__ out) {
    extern __shared__ __align__(16) unsigned dsm[];
    unsigned* sA0 = dsm;
    unsigned* sB0 = dsm + ASZ128;
    unsigned* sA1 = dsm + ASZ128 + BSZ;
    unsigned* sB1 = dsm + 2 * ASZ128 + BSZ;
    int blk = blockIdx.y;
    int tok0 = blockIdx.x * 128;
    int tid = threadIdx.x, lane = tid & 31, w = tid >> 5;
    int slab16 = (tok0 >> 7) * 16;

    cpcopy<1056>(sptr(sA0), g_rf + (size_t)(slab16 + blk) * 1056, tid);
    cpcopy<528>(sptr(sB0), g_wf_loc + (size_t)blk * 528, tid);
    cp_commit();
    cpcopy<1056>(sptr(sA1), g_tf + (size_t)(tok0 >> 7) * 1056, tid);
    cpcopy<528>(sptr(sB1), g_wf_lrA + (size_t)blk * 528, tid);
    cp_commit();

    float acc[8][4] = {};
    cp_wait<1>();
    __syncthreads();
    mma_chunk128(acc, sA0, sB0, w, lane);
    cp_wait<0>();
    __syncthreads();
    mma_chunk128(acc, sA1, sB1, w, lane);

    int g = lane >> 2, t = lane & 3;
    int r0 = tok0 + w * 16 + g;
#pragma unroll
    for (int nt = 0; nt < 8; nt++) {
        int n = blk * 64 + nt * 8 + t * 2;
        size_t i0 = (size_t)r0 * DD + n;
        size_t i1 = (size_t)(r0 + 8) * DD + n;
        float2 x0 = *reinterpret_cast<const float2*>(&x[i0]);
        float2 x1 = *reinterpret_cast<const float2*>(&x[i1]);
        *reinterpret_cast<float2*>(&out[i0]) = make_float2(x0.x + acc[nt][0], x0.y + acc[nt][1]);
        *reinterpret_cast<float2*>(&out[i1]) = make_float2(x1.x + acc[nt][2], x1.y + acc[nt][3]);
    }
}

// ---------------- launch ----------------
extern "C" void kernel_launch(void* const* d_in, const int* in_sizes, int n_in,
                              void* d_out, int out_size) {
    const float* x    = (const float*)d_in[0];
    const int*   actk = (const int*)  d_in[1];
    const float* wseq = (const float*)d_in[2];
    const float* wdep = (const float*)d_in[3];
    const float* wpost= (const float*)d_in[4];
    const float* wloc = (const float*)d_in[5];
    const float* lrA  = (const float*)d_in[6];
    const float* lrB  = (const float*)d_in[7];
    const float* lAs  = (const float*)d_in[8];
    const float* ldts = (const float*)d_in[9];
    const float* lAd  = (const float*)d_in[10];
    const float* ldtd = (const float*)d_in[11];
    float* out = (float*)d_out;

    static bool attr_done = false;
    if (!attr_done) {
        cudaFuncSetAttribute(k_g4, cudaFuncAttributeMaxDynamicSharedMemorySize, G4SMEM);
        attr_done = true;
    }

    dim3 gGemm(NTOK / 128, NBLK);    // (128, 16)
    dim3 gScan(NC, BB, 2);           // (128, 4, 2)

    k_prep<<<128 + NTOK / 8, 256>>>(x, wseq, wdep, wloc, lrA, wpost, lrB);
    k_g1<<<gGemm, 256>>>(lAd, ldtd, lAs, ldts, actk);
    k_sB<<<gScan, 256>>>(lAs, ldts);
    k_rstd<<<NTOK / 8, 256>>>();
    k_g2<<<gGemm, 256>>>();
    k_g3<<<NTOK / 64, 256>>>();
    k_g4<<<gGemm, 256, G4SMEM>>>(x, out);
}

// round 8
// speedup vs baseline: 5.1747x; 1.0095x over previous
#include <cuda_runtime.h>
#include <cuda_bf16.h>
#include <math.h>

// ---------------- problem constants ----------------
#define BB 4
#define TT_SEQ 4096
#define DD 1024
#define NTOK (BB*TT_SEQ)          // 16384
#define NBLK 16
#define BIP 192
#define RANKR 64
#define NMEM 128
#define EPSV 1.1920929e-07f
#define NT128 (NTOK/128)          // 128
#define NPOS 32                   // 128-token slabs per batch
#define NCHAIN 64                 // (b, blk) chains

// fragment-slot strides
#define ASLOT 132
#define BSLOT 66
#define BSZ (32*BSLOT)            // 2112 uints
#define ASZ64  (16*ASLOT)
#define ASZ128 (32*ASLOT)         // 4224 uints
#define SDS 66

// ---------------- scratch (device globals; no allocation) ----------------
__device__ __nv_bfloat16 g_xn   [NTOK*DD];
__device__ __nv_bfloat16 g_hn   [NTOK*DD];
__device__ float g_rsx  [NTOK];
__device__ float g_rsh  [NTOK];

// decoupled-lookback state
__device__ int   g_ticket;
__device__ int   g_state[NCHAIN*NPOS];
__device__ float g_aggv [NCHAIN*NPOS*64];
__device__ float g_incv [NCHAIN*NPOS*64];

// fragment-major activations
__device__ uint4 g_rf[NT128*16*(ASZ128/4)];
__device__ uint4 g_tf[NT128*(ASZ128/4)];

// pre-fragmented bf16 weights
__device__ uint4 g_wf_seq [NBLK*BSZ/4];
__device__ uint4 g_wf_dep [NBLK*BSZ/4];
__device__ uint4 g_wf_loc [NBLK*BSZ/4];
__device__ uint4 g_wf_lrA [NBLK*BSZ/4];
__device__ uint4 g_wf_post[NBLK*3*BSZ/4];
__device__ uint4 g_wf_lrB [16*BSZ/4];

__device__ __forceinline__ float siluf(float x) {
    return x / (1.0f + __expf(-x));
}

__device__ __forceinline__ unsigned pk(float a, float b) {
    unsigned r;
    asm("cvt.rn.bf16x2.f32 %0, %1, %2;" : "=r"(r) : "f"(b), "f"(a));
    return r;
}

__device__ __forceinline__ float decay1(const float* __restrict__ lA,
                                        const float* __restrict__ ldt, int d) {
    return fmaxf(__expf(-__expf(lA[d]) * __expf(ldt[d])), 1e-6f);
}

// ---------------- acquire/release ----------------
__device__ __forceinline__ int ld_acq(const int* p) {
    int v;
    asm volatile("ld.global.acquire.gpu.b32 %0, [%1];" : "=r"(v) : "l"(p));
    return v;
}
__device__ __forceinline__ void st_rel(int* p, int v) {
    asm volatile("st.global.release.gpu.b32 [%0], %1;" :: "l"(p), "r"(v));
}

// ---------------- cp.async helpers ----------------
__device__ __forceinline__ unsigned sptr(const void* p) {
    return (unsigned)__cvta_generic_to_shared(p);
}
__device__ __forceinline__ void cpa16(unsigned d, const void* s) {
    asm volatile("cp.async.cg.shared.global [%0], [%1], 16;" :: "r"(d), "l"(s));
}
__device__ __forceinline__ void cp_commit() {
    asm volatile("cp.async.commit_group;");
}
template<int N>
__device__ __forceinline__ void cp_wait() {
    asm volatile("cp.async.wait_group %0;" :: "n"(N));
}
template<int N4>
__device__ __forceinline__ void cpcopy(unsigned dsm, const uint4* __restrict__ src, int tid) {
#pragma unroll
    for (int i = tid; i < N4; i += 256) cpa16(dsm + i * 16, src + i);
}

// ---------------- bf16 MMA machinery ----------------
__device__ __forceinline__ void mma_bf16(float c[4], const unsigned a[4], const unsigned b[2]) {
    asm volatile("mma.sync.aligned.m16n8k16.row.col.f32.bf16.bf16.f32 "
        "{%0,%1,%2,%3}, {%4,%5,%6,%7}, {%8,%9}, {%0,%1,%2,%3};"
        : "+f"(c[0]), "+f"(c[1]), "+f"(c[2]), "+f"(c[3])
        : "r"(a[0]), "r"(a[1]), "r"(a[2]), "r"(a[3]), "r"(b[0]), "r"(b[1]));
}

__device__ __forceinline__ void putA16(unsigned* sA, int i, int j0, uint2 u) {
    int mt = i >> 4, rr = i & 15, half = rr >> 3, g = rr & 7;
    int ks = j0 >> 4, kk = j0 & 15, hi = kk >> 3, t0 = (kk & 7) >> 1;
    unsigned* p = &sA[(mt * 4 + ks) * ASLOT + (g * 4 + t0) * 4 + half + 2 * hi];
    p[0] = u.x;
    p[4] = u.y;
}

template<int M>
__device__ __forceinline__ void stageA16(unsigned* sA, const __nv_bfloat16* __restrict__ base,
                                         int rs, int tid) {
#pragma unroll
    for (int it = 0; it < M / 16; ++it) {
        int idx = tid + it * 256;
        int i  = idx >> 4;
        int j0 = (idx & 15) << 2;
        uint2 u = *reinterpret_cast<const uint2*>(base + (size_t)i * rs + j0);
        putA16(sA, i, j0, u);
    }
}

__device__ __forceinline__ void mma_chunk128(float acc[8][4], const unsigned* sA,
                                             const unsigned* sB, int w, int lane) {
#pragma unroll
    for (int ks = 0; ks < 4; ks++) {
        unsigned a[4];
        *reinterpret_cast<uint4*>(a) =
            *reinterpret_cast<const uint4*>(&sA[(w * 4 + ks) * ASLOT + lane * 4]);
#pragma unroll
        for (int nt = 0; nt < 8; nt++) {
            unsigned b[2];
            *reinterpret_cast<uint2*>(b) =
                *reinterpret_cast<const uint2*>(&sB[(nt * 4 + ks) * BSLOT + lane * 2]);
            mma_bf16(acc[nt], a, b);
        }
    }
}

__device__ __forceinline__ void mma_chunk64(float acc[4][4], const unsigned* sA,
                                            const unsigned* sB, int wm, int wn, int lane) {
#pragma unroll
    for (int ks = 0; ks < 4; ks++) {
        unsigned a[4];
        *reinterpret_cast<uint4*>(a) =
            *reinterpret_cast<const uint4*>(&sA[(wm * 4 + ks) * ASLOT + lane * 4]);
#pragma unroll
        for (int nt = 0; nt < 4; nt++) {
            unsigned b[2];
            *reinterpret_cast<uint2*>(b) =
                *reinterpret_cast<const uint2*>(&sB[((wn * 4 + nt) * 4 + ks) * BSLOT + lane * 2]);
            mma_bf16(acc[nt], a, b);
        }
    }
}

// ---------------- prep: flags + weight fragmentation + x stats ----------------
__global__ void __launch_bounds__(256) k_prep(const float* __restrict__ x,
                                              const float* __restrict__ wseq,
                                              const float* __restrict__ wdep,
                                              const float* __restrict__ wloc,
                                              const float* __restrict__ lrA,
                                              const float* __restrict__ wpost,
                                              const float* __restrict__ lrB) {
    int tid = threadIdx.x;
    if (blockIdx.x == 0) {
        if (tid == 0) g_ticket = 0;
        for (int i = tid; i < NCHAIN * NPOS; i += 256) g_state[i] = 0;
    }
    if (blockIdx.x < 128) {
        int t = blockIdx.x;
        const float* src;
        unsigned* dst;
        int rs;
        if (t < 16)       { src = wseq + (size_t)t * 4096; dst = (unsigned*)g_wf_seq + t * BSZ; rs = 64; }
        else if (t < 32)  { int b = t - 16; src = wdep + (size_t)b * 4096; dst = (unsigned*)g_wf_dep + b * BSZ; rs = 64; }
        else if (t < 48)  { int b = t - 32; src = wloc + (size_t)b * 4096; dst = (unsigned*)g_wf_loc + b * BSZ; rs = 64; }
        else if (t < 64)  { int b = t - 48; src = lrA + (size_t)b * 4096;  dst = (unsigned*)g_wf_lrA + b * BSZ; rs = 64; }
        else if (t < 112) { int i = t - 64; int b = i / 3, kt = i % 3;
                            src = wpost + (size_t)b * 64 * BIP + kt * 64;
                            dst = (unsigned*)g_wf_post + i * BSZ; rs = BIP; }
        else              { int kt = t - 112; src = lrB + kt * 64; dst = (unsigned*)g_wf_lrB + kt * BSZ; rs = DD; }
#pragma unroll
        for (int it = 0; it < 4; ++it) {
            int idx = tid + it * 256;
            int n  = idx >> 4;
            int k0 = (idx & 15) << 2;
            float4 v = *reinterpret_cast<const float4*>(src + (size_t)n * rs + k0);
            int nt = n >> 3, g = n & 7;
            int ks = k0 >> 4, kk = k0 & 15, hi = kk >> 3, t0 = (kk & 7) >> 1;
            unsigned* p = &dst[(nt * 4 + ks) * BSLOT + (g * 4 + t0) * 2 + hi];
            p[0] = pk(v.x, v.y);
            p[2] = pk(v.z, v.w);
        }
    } else {
        int w = tid >> 5, lane = tid & 31;
        int tok = (blockIdx.x - 128) * 8 + w;
        const float4* xr = reinterpret_cast<const float4*>(x + (size_t)tok * DD);
        float4 v[8];
        float ss = 0.0f;
#pragma unroll
        for (int i = 0; i < 8; i++) {
            v[i] = xr[lane + i * 32];
            ss += v[i].x * v[i].x + v[i].y * v[i].y + v[i].z * v[i].z + v[i].w * v[i].w;
        }
#pragma unroll
        for (int off = 16; off > 0; off >>= 1) ss += __shfl_xor_sync(0xffffffffu, ss, off);
        ss = __shfl_sync(0xffffffffu, ss, 0);
        float sc = rsqrtf(ss * (1.0f / DD) + EPSV);
        if (lane == 0) g_rsx[tok] = sc;
        uint2* xo = reinterpret_cast<uint2*>(g_xn + (size_t)tok * DD);
#pragma unroll
        for (int i = 0; i < 8; i++) {
            uint2 o;
            o.x = pk(v[i].x * sc, v[i].y * sc);
            o.y = pk(v[i].z * sc, v[i].w * sc);
            xo[lane + i * 32] = o;
        }
    }
}

// ---------------- gain helper ----------------
__device__ __forceinline__ float gain_of(int gch, float Kf, const float* __restrict__ lAd,
                                         const float* __restrict__ ldtd) {
    if (gch < NMEM) return Kf;
    float a1 = __expf(-__expf(lAd[gch - NMEM]) * __expf(ldtd[gch - NMEM]));
    float om = 1.0f - a1;
    if (fabsf(om) < 1e-6f) return Kf;
    return (1.0f - __expf(Kf * __logf(a1))) / fmaxf(om, 1e-8f);
}

// ---------------- G1S: GEMMs + single-pass scan (decoupled lookback) -> g_hn ----------------
// dyn smem layout (uints):
//  [0, 4224)        sA (staging)        | aliased after MMA: sD fp32[128][66]
//  [4224, 6336)     sB1
//  [6336, 8448)     sB2                 | sD continues to 8448
//  [8448, 12672)    sHD packed bf16 [128][33]
//  [12672, 13248)   sS[4][64] | sQ[4][64] | sC[64]  (floats)
#define G1SMEM (13248 * 4)

__global__ void __launch_bounds__(256) k_g1s(const float* __restrict__ lAd,
                                             const float* __restrict__ ldtd,
                                             const float* __restrict__ lAs,
                                             const float* __restrict__ ldts,
                                             const int* __restrict__ kptr) {
    extern __shared__ __align__(16) unsigned dyn[];
    __shared__ int s_ticket;
    int tid = threadIdx.x, lane = tid & 31, w = tid >> 5;

    if (tid == 0) s_ticket = atomicAdd(&g_ticket, 1);
    __syncthreads();
    int ticket = s_ticket;
    int chain = ticket & (NCHAIN - 1);
    int pos   = ticket >> 6;
    int b = chain >> 4, blk = chain & 15;
    int tok0 = (b * NPOS + pos) * 128;

    unsigned* sA  = dyn;
    unsigned* sB1 = dyn + ASZ128;
    unsigned* sB2 = dyn + ASZ128 + BSZ;

    cpcopy<528>(sptr(sB1), g_wf_seq + (size_t)blk * 528, tid);
    cpcopy<528>(sptr(sB2), g_wf_dep + (size_t)blk * 528, tid);
    cp_commit();
    stageA16<128>(sA, g_xn + (size_t)tok0 * DD + blk * 64, DD, tid);
    cp_wait<0>();
    __syncthreads();

    float as_[8][4] = {}, ad_[8][4] = {};
#pragma unroll
    for (int ks = 0; ks < 4; ks++) {
        unsigned a[4];
        *reinterpret_cast<uint4*>(a) =
            *reinterpret_cast<const uint4*>(&sA[(w * 4 + ks) * ASLOT + lane * 4]);
#pragma unroll
        for (int nt = 0; nt < 8; nt++) {
            int off = (nt * 4 + ks) * BSLOT + lane * 2;
            unsigned bb[2];
            *reinterpret_cast<uint2*>(bb) = *reinterpret_cast<const uint2*>(&sB1[off]);
            mma_bf16(as_[nt], a, bb);
            *reinterpret_cast<uint2*>(bb) = *reinterpret_cast<const uint2*>(&sB2[off]);
            mma_bf16(ad_[nt], a, bb);
        }
    }
    __syncthreads();                  // staging dead; alias scan buffers

    float*    sD  = reinterpret_cast<float*>(dyn);     // [128][66] fp32
    unsigned* sHD = dyn + 8448;                        // [128][33] bf16x2
    float*    sS  = reinterpret_cast<float*>(dyn + 12672);   // [4][64]
    float*    sQ  = sS + 256;                                 // [4][64]
    float*    sC  = sQ + 256;                                 // [64]

    // epilogue: silu -> drive (fp32, smem) ; gain*silu -> hd (bf16x2, smem)
    {
        float Kf = (float)(*kptr);
        int g = lane >> 2, t = lane & 3;
        int rl0 = w * 16 + g;
#pragma unroll
        for (int nt = 0; nt < 8; nt++) {
            int nl = nt * 8 + t * 2;
            int gch = blk * 64 + nl;
            float gn0 = gain_of(gch, Kf, lAd, ldtd);
            float gn1 = gain_of(gch + 1, Kf, lAd, ldtd);
            *reinterpret_cast<float2*>(&sD[rl0 * SDS + nl]) =
                make_float2(siluf(as_[nt][0]), siluf(as_[nt][1]));
            *reinterpret_cast<float2*>(&sD[(rl0 + 8) * SDS + nl]) =
                make_float2(siluf(as_[nt][2]), siluf(as_[nt][3]));
            sHD[rl0 * 33 + (nl >> 1)] =
                pk(gn0 * siluf(ad_[nt][0]), gn1 * siluf(ad_[nt][1]));
            sHD[(rl0 + 8) * 33 + (nl >> 1)] =
                pk(gn0 * siluf(ad_[nt][2]), gn1 * siluf(ad_[nt][3]));
        }
    }
    __syncthreads();

    // scan thread mapping: ch = tid & 63 (two warps per quarter), q = tid >> 6
    int ch = tid & 63, q = tid >> 6;
    int gch = blk * 64 + ch;
    float a  = decay1(lAs, ldts, gch);
    float la = __logf(a);
    float a32 = __expf(32.0f * la);
    float aT  = __expf(128.0f * la);

    // local quarter scan (in place): sD <- quarter-local inclusive
    {
        float y = 0.0f;
        int base = q * 32;
#pragma unroll 8
        for (int s = 0; s < 32; s++) {
            float* p = &sD[(base + s) * SDS + ch];
            y = fmaf(a, y, *p);
            *p = y;
        }
        sS[q * 64 + ch] = y;
    }
    __syncthreads();

    // quarter combine + aggregate publish
    float agg = 0.0f;
    if (tid < 64) {
        float C = 0.0f;
#pragma unroll
        for (int q2 = 0; q2 < 4; q2++) {
            sQ[q2 * 64 + tid] = C;
            C = fmaf(C, a32, sS[q2 * 64 + tid]);
        }
        agg = C;
        g_aggv[(size_t)(chain * NPOS + pos) * 64 + tid] = agg;
    }
    __syncthreads();
    if (tid == 0) {
        __threadfence();
        st_rel(&g_state[chain * NPOS + pos], 1);
    }

    // lookback
    if (tid < 64) {
        float carry = 0.0f;
        if (pos > 0) {
            float f = 1.0f;
            int p = pos - 1;
            while (true) {
                int st;
                do { st = ld_acq(&g_state[chain * NPOS + p]); } while (st == 0);
                if (st == 2) {
                    carry = fmaf(f, g_incv[(size_t)(chain * NPOS + p) * 64 + tid], carry);
                    break;
                }
                carry = fmaf(f, g_aggv[(size_t)(chain * NPOS + p) * 64 + tid], carry);
                f *= aT;
                if (--p < 0) break;
            }
        }
        sC[tid] = carry;
        if (pos < NPOS - 1)
            g_incv[(size_t)(chain * NPOS + pos) * 64 + tid] = fmaf(carry, aT, agg);
    }
    __syncthreads();
    if (tid == 0 && pos < NPOS - 1) {
        __threadfence();
        st_rel(&g_state[chain * NPOS + pos], 2);
    }

    // final combine: h = local + eff_carry * a^(s+1) + hd   (in place into sD)
    {
        float carry = sC[ch];
        float a64 = a32 * a32;
        float aq = (q == 0) ? 1.0f : (q == 1) ? a32 : (q == 2) ? a64 : a64 * a32;
        float eff = fmaf(carry, aq, sQ[q * 64 + ch]);
        float pw = eff * a;
        int base = q * 32;
#pragma unroll 8
        for (int s = 0; s < 32; s++) {
            int row = base + s;
            unsigned hu = sHD[row * 33 + (ch >> 1)];
            float2 hp = __bfloat1622float2(*reinterpret_cast<__nv_bfloat162*>(&hu));
            float hdv = (ch & 1) ? hp.y : hp.x;
            float* p = &sD[row * SDS + ch];
            *p = *p + pw + hdv;
            pw *= a;
        }
    }
    __syncthreads();

    // pack + coalesced store of h -> g_hn
#pragma unroll
    for (int it = 0; it < 16; it++) {
        int idx = tid + it * 256;        // 4096 = 128 rows x 32 uint pairs
        int row = idx >> 5;
        int c2  = idx & 31;
        float h0 = sD[row * SDS + c2 * 2];
        float h1 = sD[row * SDS + c2 * 2 + 1];
        *reinterpret_cast<unsigned*>(&g_hn[(size_t)(tok0 + row) * DD + blk * 64 + c2 * 2]) =
            pk(h0, h1);
    }
}

// ---------------- rstd: warp-per-token over g_hn -> g_rsh ----------------
__global__ void __launch_bounds__(256) k_rstd() {
    int w = threadIdx.x >> 5, lane = threadIdx.x & 31;
    int tok = blockIdx.x * 8 + w;
    const uint4* hr = reinterpret_cast<const uint4*>(g_hn + (size_t)tok * DD);
    float ss = 0.0f;
#pragma unroll
    for (int i = 0; i < 4; i++) {
        uint4 u = hr[lane + i * 32];
        float2 a0 = __bfloat1622float2(*reinterpret_cast<__nv_bfloat162*>(&u.x));
        float2 a1 = __bfloat1622float2(*reinterpret_cast<__nv_bfloat162*>(&u.y));
        float2 a2 = __bfloat1622float2(*reinterpret_cast<__nv_bfloat162*>(&u.z));
        float2 a3 = __bfloat1622float2(*reinterpret_cast<__nv_bfloat162*>(&u.w));
        ss += a0.x * a0.x + a0.y * a0.y + a1.x * a1.x + a1.y * a1.y
            + a2.x * a2.x + a2.y * a2.y + a3.x * a3.x + a3.y * a3.y;
    }
#pragma unroll
    for (int off = 16; off > 0; off >>= 1) ss += __shfl_xor_sync(0xffffffffu, ss, off);
    if (lane == 0) g_rsh[tok] = rsqrtf(ss * (1.0f / DD) + EPSV);
}

// ---------------- G2 helpers ----------------
struct CatRegs { uint2 u[8]; float sc[8]; };

__device__ __forceinline__ void catA_load(CatRegs& r, int tok0, int gcat0, int tid) {
#pragma unroll
    for (int it = 0; it < 8; ++it) {
        int idx = tid + it * 256;
        int i  = idx >> 4;
        int j0 = (idx & 15) << 2;
        int gcat = gcat0 + j0;
        int tok = tok0 + i;
        uint2 u;
        float sc = 1.0f;
        if (gcat < 1024) {
            u = *reinterpret_cast<const uint2*>(&g_hn[(size_t)tok * DD + gcat]);
            sc = g_rsh[tok];
        } else if (gcat < 2048) {
            u = *reinterpret_cast<const uint2*>(&g_xn[(size_t)tok * DD + (gcat - 1024)]);
        } else {
            if ((tok & (TT_SEQ - 1)) == 0) { u.x = 0u; u.y = 0u; }
            else u = *reinterpret_cast<const uint2*>(&g_xn[(size_t)(tok - 1) * DD + (gcat - 2048)]);
        }
        r.u[it] = u;
        r.sc[it] = sc;
    }
}

__device__ __forceinline__ void catA_sts(unsigned* sA, const CatRegs& r, int gcat0, int tid) {
#pragma unroll
    for (int it = 0; it < 8; ++it) {
        int idx = tid + it * 256;
        int i  = idx >> 4;
        int j0 = (idx & 15) << 2;
        int gcat = gcat0 + j0;
        uint2 u = r.u[it];
        if (gcat < 1024) {
            float sc = r.sc[it];
            float2 lo = __bfloat1622float2(*reinterpret_cast<const __nv_bfloat162*>(&u.x));
            float2 hi = __bfloat1622float2(*reinterpret_cast<const __nv_bfloat162*>(&u.y));
            u.x = pk(lo.x * sc, lo.y * sc);
            u.y = pk(hi.x * sc, hi.y * sc);
        }
        putA16(sA, i, j0, u);
    }
}

// ---------------- G2 ----------------
__global__ void __launch_bounds__(256) k_g2() {
    __shared__ __align__(16) unsigned sA[ASZ128];
    __shared__ __align__(16) unsigned sB[2][BSZ];
    int blk = blockIdx.y;
    int tok0 = blockIdx.x * 128;
    int tid = threadIdx.x, lane = tid & 31, w = tid >> 5;
    const uint4* wp = g_wf_post + (size_t)(blk * 3) * 528;

    cpcopy<528>(sptr(sB[0]), wp, tid);       cp_commit();
    cpcopy<528>(sptr(sB[1]), wp + 528, tid); cp_commit();

    CatRegs r;
    catA_load(r, tok0, blk * BIP, tid);
    catA_sts(sA, r, blk * BIP, tid);
    cp_wait<1>();
    __syncthreads();

    float acc[8][4] = {};
    catA_load(r, tok0, blk * BIP + 64, tid);
    mma_chunk128(acc, sA, sB[0], w, lane);
    __syncthreads();
    cpcopy<528>(sptr(sB[0]), wp + 1056, tid); cp_commit();
    catA_sts(sA, r, blk * BIP + 64, tid);
    cp_wait<1>();
    __syncthreads();
    catA_load(r, tok0, blk * BIP + 128, tid);
    mma_chunk128(acc, sA, sB[1], w, lane);
    __syncthreads();
    catA_sts(sA, r, blk * BIP + 128, tid);
    cp_wait<0>();
    __syncthreads();
    mma_chunk128(acc, sA, sB[0], w, lane);

    int g = lane >> 2, t = lane & 3;
    unsigned* rf = (unsigned*)g_rf + ((size_t)((tok0 >> 7) * 16 + blk)) * ASZ128;
#pragma unroll
    for (int nt = 0; nt < 8; nt++) {
        int ks = nt >> 1, hi = nt & 1;
        unsigned* p = rf + (w * 4 + ks) * ASLOT + (g * 4 + t) * 4 + 2 * hi;
        p[0] = pk(siluf(acc[nt][0]), siluf(acc[nt][1]));
        p[1] = pk(siluf(acc[nt][2]), siluf(acc[nt][3]));
    }
}

// ---------------- G3 ----------------
__device__ __forceinline__ void g3_issue(unsigned dA, unsigned dB, int slab16, int halfoff,
                                         int kt, int tid) {
    cpcopy<528>(dA, g_rf + (size_t)(slab16 + kt) * 1056 + halfoff, tid);
    cpcopy<528>(dB, g_wf_lrB + (size_t)kt * 528, tid);
    cp_commit();
}

__global__ void __launch_bounds__(256) k_g3() {
    __shared__ __align__(16) unsigned smem[2 * ASZ64 + 2 * BSZ];
    unsigned* sAb[2] = { smem, smem + ASZ64 };
    unsigned* sBb[2] = { smem + 2 * ASZ64, smem + 2 * ASZ64 + BSZ };
    int tok0 = blockIdx.x * 64;
    int tid = threadIdx.x, lane = tid & 31, w = tid >> 5, wm = w & 3, wn = w >> 2;
    int slab16 = (tok0 >> 7) * 16;
    int halfoff = ((tok0 >> 6) & 1) * 528;

    g3_issue(sptr(sAb[0]), sptr(sBb[0]), slab16, halfoff, 0, tid);
    g3_issue(sptr(sAb[1]), sptr(sBb[1]), slab16, halfoff, 1, tid);

    float acc[4][4] = {};
#pragma unroll
    for (int kt = 0; kt < 16; kt++) {
        if (kt < 15) cp_wait<1>(); else cp_wait<0>();
        __syncthreads();
        mma_chunk64(acc, sAb[kt & 1], sBb[kt & 1], wm, wn, lane);
        __syncthreads();
        if (kt + 2 < 16)
            g3_issue(sptr(sAb[kt & 1]), sptr(sBb[kt & 1]), slab16, halfoff, kt + 2, tid);
    }

    int g = lane >> 2, t = lane & 3;
    int mtg = ((tok0 & 64) >> 4) + wm;
    unsigned* tf = (unsigned*)g_tf + (size_t)(tok0 >> 7) * ASZ128;
#pragma unroll
    for (int nt = 0; nt < 4; nt++) {
        int ng = wn * 4 + nt;
        int ks = ng >> 1, hi = ng & 1;
        unsigned* p = tf + (mtg * 4 + ks) * ASLOT + (g * 4 + t) * 4 + 2 * hi;
        p[0] = pk(acc[nt][0], acc[nt][1]);
        p[1] = pk(acc[nt][2], acc[nt][3]);
    }
}

// ---------------- G4 ----------------
#define G4SMEM (2 * (ASZ128 + BSZ) * 4)

__global__ void __launch_bounds__(256) k_g4(const float* __restrict__ x,
                                            float* __restrict__ out) {
    extern __shared__ __align__(16) unsigned dsm[];
    unsigned* sA0 = dsm;
    unsigned* sB0 = dsm + ASZ128;
    unsigned* sA1 = dsm + ASZ128 + BSZ;
    unsigned* sB1 = dsm + 2 * ASZ128 + BSZ;
    int blk = blockIdx.y;
    int tok0 = blockIdx.x * 128;
    int tid = threadIdx.x, lane = tid & 31, w = tid >> 5;
    int slab16 = (tok0 >> 7) * 16;

    cpcopy<1056>(sptr(sA0), g_rf + (size_t)(slab16 + blk) * 1056, tid);
    cpcopy<528>(sptr(sB0), g_wf_loc + (size_t)blk * 528, tid);
    cp_commit();
    cpcopy<1056>(sptr(sA1), g_tf + (size_t)(tok0 >> 7) * 1056, tid);
    cpcopy<528>(sptr(sB1), g_wf_lrA + (size_t)blk * 528, tid);
    cp_commit();

    float acc[8][4] = {};
    cp_wait<1>();
    __syncthreads();
    mma_chunk128(acc, sA0, sB0, w, lane);
    cp_wait<0>();
    __syncthreads();
    mma_chunk128(acc, sA1, sB1, w, lane);

    int g = lane >> 2, t = lane & 3;
    int r0 = tok0 + w * 16 + g;
#pragma unroll
    for (int nt = 0; nt < 8; nt++) {
        int n = blk * 64 + nt * 8 + t * 2;
        size_t i0 = (size_t)r0 * DD + n;
        size_t i1 = (size_t)(r0 + 8) * DD + n;
        float2 x0 = *reinterpret_cast<const float2*>(&x[i0]);
        float2 x1 = *reinterpret_cast<const float2*>(&x[i1]);
        *reinterpret_cast<float2*>(&out[i0]) = make_float2(x0.x + acc[nt][0], x0.y + acc[nt][1]);
        *reinterpret_cast<float2*>(&out[i1]) = make_float2(x1.x + acc[nt][2], x1.y + acc[nt][3]);
    }
}

// ---------------- launch ----------------
extern "C" void kernel_launch(void* const* d_in, const int* in_sizes, int n_in,
                              void* d_out, int out_size) {
    const float* x    = (const float*)d_in[0];
    const int*   actk = (const int*)  d_in[1];
    const float* wseq = (const float*)d_in[2];
    const float* wdep = (const float*)d_in[3];
    const float* wpost= (const float*)d_in[4];
    const float* wloc = (const float*)d_in[5];
    const float* lrA  = (const float*)d_in[6];
    const float* lrB  = (const float*)d_in[7];
    const float* lAs  = (const float*)d_in[8];
    const float* ldts = (const float*)d_in[9];
    const float* lAd  = (const float*)d_in[10];
    const float* ldtd = (const float*)d_in[11];
    float* out = (float*)d_out;

    static bool attr_done = false;
    if (!attr_done) {
        cudaFuncSetAttribute(k_g4, cudaFuncAttributeMaxDynamicSharedMemorySize, G4SMEM);
        cudaFuncSetAttribute(k_g1s, cudaFuncAttributeMaxDynamicSharedMemorySize, G1SMEM);
        attr_done = true;
    }

    dim3 gGemm(NTOK / 128, NBLK);    // (128, 16)

    k_prep<<<128 + NTOK / 8, 256>>>(x, wseq, wdep, wloc, lrA, wpost, lrB);
    k_g1s<<<NT128 * 16, 256, G1SMEM>>>(lAd, ldtd, lAs, ldts, actk);
    k_rstd<<<NTOK / 8, 256>>>();
    k_g2<<<gGemm, 256>>>();
    k_g3<<<NTOK / 64, 256>>>();
    k_g4<<<gGemm, 256, G4SMEM>>>(x, out);
}